// round 6
// baseline (speedup 1.0000x reference)
#include <cuda_runtime.h>

#define NN 1024
#define EPSF 1e-5f
#define INFF 1e5f

typedef unsigned long long u64;

// ---------------- device scratch --------------------------------------------------
__device__ float g_A[NN * 64];                  // h@ew1[0:64] + eb1
__device__ float g_Bt[64 * NN];                 // h@ew1[64:128], k-major [k][j]
__device__ float g_slog[NN * NN];
__device__ float g_w[NN * NN];
__device__ float g_wsum[NN];
__device__ float g_cv[NN * 64];
__device__ float g_combos[NN * 96];
__device__ float g_xacc[NN * 3];
// folded weights
__device__ __align__(16) float g_Wcf[64 * 128]; // row k: [ew2@cw1 | ew2@fw1]
__device__ float g_bc[64];
__device__ float g_bf1a[64];
__device__ float g_waw[64];
__device__ float g_baw[1];
__device__ float g_Cw[64];

// ---------------- f32x2 helpers ---------------------------------------------------
__device__ __forceinline__ u64 pk2(float x, float y) {
    u64 r;
    asm("mov.b64 %0,{%1,%2};" : "=l"(r) : "r"(__float_as_uint(x)), "r"(__float_as_uint(y)));
    return r;
}
__device__ __forceinline__ float2 upk2(u64 p) {
    unsigned lo, hi;
    asm("mov.b64 {%0,%1},%2;" : "=r"(lo), "=r"(hi) : "l"(p));
    return make_float2(__uint_as_float(lo), __uint_as_float(hi));
}
__device__ __forceinline__ void fma2(u64& a, u64 x, u64 w) {
    asm("fma.rn.f32x2 %0,%1,%2,%0;" : "+l"(a) : "l"(x), "l"(w));
}
__device__ __forceinline__ float silu_f(float v) {
    return __fdividef(v, 1.f + __expf(-v));
}

__device__ __forceinline__ float blk_red(float v, float* red, int tid, bool ismax) {
    red[tid] = v;
    __syncthreads();
#pragma unroll
    for (int s = 128; s >= 1; s >>= 1) {
        if (tid < s) red[tid] = ismax ? fmaxf(red[tid], red[tid + s]) : red[tid] + red[tid + s];
        __syncthreads();
    }
    float r = red[0];
    __syncthreads();
    return r;
}

// ---------------- K-zero ----------------------------------------------------------
__global__ void k_zero() {
    int idx = blockIdx.x * blockDim.x + threadIdx.x;
    if (idx < NN * 64) g_cv[idx] = 0.f;
    if (idx < NN * 96) g_combos[idx] = 0.f;
    if (idx < NN * 3) g_xacc[idx] = 0.f;
}

// ---------------- k_fold ----------------------------------------------------------
__global__ void k_fold(const float* __restrict__ ew1, const float* __restrict__ ew2,
                       const float* __restrict__ eb2, const float* __restrict__ cw1,
                       const float* __restrict__ cb1, const float* __restrict__ fw1,
                       const float* __restrict__ aw, const float* __restrict__ ab) {
    int b = blockIdx.x, tid = threadIdx.x;  // 64 threads
    if (b < 64) {
        __shared__ float se[64];
        se[tid] = ew2[b * 64 + tid];
        __syncthreads();
        float ac = 0.f, af = 0.f;
#pragma unroll 8
        for (int k = 0; k < 64; k++) {
            float e = se[k];
            ac += e * cw1[k * 64 + tid];
            af += e * fw1[k * 64 + tid];
        }
        g_Wcf[b * 128 + tid] = ac;
        g_Wcf[b * 128 + 64 + tid] = af;
    } else {
        float sw = 0.f;
        for (int k = 0; k < 64; k++) sw += ew2[tid * 64 + k] * aw[k];
        g_waw[tid] = sw;
        float bc = cb1[tid], bf = 0.f;
        for (int k = 0; k < 64; k++) {
            bc += eb2[k] * cw1[k * 64 + tid];
            bf += eb2[k] * fw1[k * 64 + tid];
        }
        g_bc[tid] = bc;
        g_bf1a[tid] = bf;
        g_Cw[tid] = ew1[128 * 64 + tid];
        if (tid == 0) {
            float s = ab[0];
            for (int k = 0; k < 64; k++) s += eb2[k] * aw[k];
            g_baw[0] = s;
        }
    }
}

// ---------------- K0 --------------------------------------------------------------
__global__ void k_node_pre(const float* __restrict__ h, const float* __restrict__ ew1,
                           const float* __restrict__ eb1) {
    __shared__ float hr[64];
    int i = blockIdx.x, tid = threadIdx.x;
    hr[tid] = h[i * 64 + tid];
    __syncthreads();
    float a = eb1[tid], b = 0.f;
#pragma unroll 8
    for (int m = 0; m < 64; m++) {
        float hm = hr[m];
        a += hm * ew1[m * 64 + tid];
        b += hm * ew1[(64 + m) * 64 + tid];
    }
    g_A[i * 64 + tid] = a;
    g_Bt[tid * NN + i] = b;
}

// ---------------- K1: semantic logits ---------------------------------------------
__global__ void __launch_bounds__(256) k_edge1(const float* __restrict__ x) {
    __shared__ float sA[64], sC[64], sW[64], sXi[3], sBaw[1];
    int i = blockIdx.y, tid = threadIdx.x;
    int j = blockIdx.x * 256 + tid;
    if (tid < 64) {
        sA[tid] = g_A[i * 64 + tid];
        sC[tid] = g_Cw[tid];
        sW[tid] = g_waw[tid];
    }
    if (tid < 3) sXi[tid] = x[i * 3 + tid];
    if (tid == 0) sBaw[0] = g_baw[0];
    __syncthreads();

    float dx = sXi[0] - x[j * 3 + 0];
    float dy = sXi[1] - x[j * 3 + 1];
    float dz = sXi[2] - x[j * 3 + 2];
    float nrm = sqrtf(dx * dx + dy * dy + dz * dz + EPSF);

    float slog = sBaw[0];
#pragma unroll 8
    for (int k = 0; k < 64; k++) {
        float b = g_Bt[k * NN + j];
        slog += silu_f(sA[k] + b + nrm * sC[k]) * sW[k];
    }
    slog = (slog > 0.f) ? slog : 0.01f * slog;
    g_slog[i * NN + j] = slog;
}

// ---------------- K3: fused softmax combine ---------------------------------------
__global__ void k_attn(const float* __restrict__ x, const float* __restrict__ lg) {
    __shared__ float sls[NN], sle[NN];
    __shared__ float red[256];
    int i = blockIdx.x, tid = threadIdx.x;
    float gamma = __expf(lg[0]);
    float xi0 = x[i * 3 + 0], xi1 = x[i * 3 + 1], xi2 = x[i * 3 + 2];

    for (int j = tid; j < NN; j += 256) {
        float dx = xi0 - x[j * 3 + 0];
        float dy = xi1 - x[j * 3 + 1];
        float dz = xi2 - x[j * 3 + 2];
        float nrm = sqrtf(dx * dx + dy * dy + dz * dz + EPSF);
        float diag = (j == i) ? INFF : 0.f;
        sle[j] = -(nrm + diag) * gamma;
        sls[j] = g_slog[i * NN + j] - diag;
    }
    __syncthreads();

    float m = -3.4e38f;
    for (int j = tid; j < NN; j += 256) m = fmaxf(m, sls[j]);
    m = blk_red(m, red, tid, true);

    float ze = 0.f, zs = 0.f, tt = 0.f;
    for (int j = tid; j < NN; j += 256) {
        float le = sle[j], ls = sls[j] - m;
        ze += __expf(le);
        zs += __expf(ls);
        tt += __expf(le + ls);
    }
    ze = blk_red(ze, red, tid, false);
    zs = blk_red(zs, red, tid, false);
    tt = blk_red(tt, red, tid, false);

    float inv = 1.f / (tt + EPSF * ze * zs);
    for (int j = tid; j < NN; j += 256)
        g_w[i * NN + j] = __expf(sle[j] + sls[j] - m) * inv;
    if (tid == 0) g_wsum[i] = tt * inv;
}

// ---------------- K4: cooperative-GEMM pair kernel --------------------------------
// smem float offsets
#define SVR      132
#define OFF_SV   0               // 64 x 132 (v -> S -> coeff stage)
#define OFF_W    8448            // 64 x 128
#define OFF_F2   16640           // 64 x 32
#define OFF_A    18688
#define OFF_CD   18752
#define OFF_BC   18816
#define OFF_CW2  18880
#define OFF_BF   18944
#define OFF_FB1  19008
#define OFF_FB2  19072
#define OFF_WJ   19104           // 128
#define OFF_PHI  19232           // 128
#define OFF_DIR  19360           // 3 x 128
#define OFF_DXR  19744           // 3 x 128
#define OFF_CVP  20128           // 64 x 4
#define OFF_XI   20384
#define K4_FLOATS 20388

__global__ void __launch_bounds__(256, 2) k_pair(const float* __restrict__ x,
                                                 const float* __restrict__ fw2,
                                                 const float* __restrict__ fb1,
                                                 const float* __restrict__ fb2,
                                                 const float* __restrict__ cw2) {
    extern __shared__ __align__(16) float dyn[];
    float* sv = dyn + OFF_SV;

    int i = blockIdx.y, tid = threadIdx.x;
    int jl = tid & 127, kh = tid >> 7;
    int jg = blockIdx.x * 128 + jl;

    for (int t = tid; t < 8192; t += 256) dyn[OFF_W + t] = g_Wcf[t];
    for (int t = tid; t < 2048; t += 256) dyn[OFF_F2 + t] = fw2[t];
    if (tid < 64) {
        dyn[OFF_A + tid] = g_A[i * 64 + tid];
        dyn[OFF_CD + tid] = g_Cw[tid];
        dyn[OFF_BC + tid] = g_bc[tid];
        dyn[OFF_CW2 + tid] = cw2[tid];
        dyn[OFF_BF + tid] = g_bf1a[tid];
        dyn[OFF_FB1 + tid] = fb1[tid];
    }
    if (tid < 32) dyn[OFF_FB2 + tid] = fb2[tid];
    if (tid < 3) dyn[OFF_XI + tid] = x[i * 3 + tid];
    __syncthreads();

    // ---- phase A: geometry + v (each (kh,jl) thread does 32 k for its j) ----
    float dx0 = dyn[OFF_XI + 0] - x[jg * 3 + 0];
    float dx1 = dyn[OFF_XI + 1] - x[jg * 3 + 1];
    float dx2 = dyn[OFF_XI + 2] - x[jg * 3 + 2];
    float nrm = sqrtf(dx0 * dx0 + dx1 * dx1 + dx2 * dx2 + EPSF);
    if (kh == 0) {
        float inv1 = __fdividef(1.f, nrm + 1.f);
        dyn[OFF_DXR + 0 * 128 + jl] = dx0;
        dyn[OFF_DXR + 1 * 128 + jl] = dx1;
        dyn[OFF_DXR + 2 * 128 + jl] = dx2;
        dyn[OFF_DIR + 0 * 128 + jl] = dx0 * inv1;
        dyn[OFF_DIR + 1 * 128 + jl] = dx1 * inv1;
        dyn[OFF_DIR + 2 * 128 + jl] = dx2 * inv1;
        dyn[OFF_WJ + jl] = g_w[i * NN + jg];
        dyn[OFF_PHI + jl] = 0.f;
    }
    {
        int k0 = kh * 32;
#pragma unroll 8
        for (int k = k0; k < k0 + 32; k++) {
            float b = g_Bt[k * NN + jg];
            sv[k * SVR + jl] = silu_f(dyn[OFF_A + k] + b + nrm * dyn[OFF_CD + k]);
        }
    }
    __syncthreads();

    // ---- cv = sum_j w*v (done now so sv can be reused later) ----
    {
        int k = tid & 63, part = tid >> 6;
        const float* vp = sv + k * SVR + part * 32;
        const float* wp = dyn + OFF_WJ + part * 32;
        float sacc = 0.f;
#pragma unroll 8
        for (int jj = 0; jj < 32; jj++) sacc += wp[jj] * vp[jj];
        dyn[OFF_CVP + k * 4 + part] = sacc;
    }
    __syncthreads();
    if (tid < 64) {
        float4 p = *reinterpret_cast<const float4*>(dyn + OFF_CVP + tid * 4);
        atomicAdd(&g_cv[i * 64 + tid], p.x + p.y + p.z + p.w);
    }

    // ---- GEMM1: P[128j x 128o] = V[128x64] @ Wcf[64x128], 8j x 8o per thread ----
    int tjg = tid >> 4;          // 16 j-groups of 8
    int tog = tid & 15;          // 16 o-groups of 8
    u64 acc[32];
#pragma unroll
    for (int t = 0; t < 32; t++) acc[t] = 0ull;

#pragma unroll 8
    for (int kk = 0; kk < 64; kk++) {
        const float4* vrow = reinterpret_cast<const float4*>(sv + kk * SVR + tjg * 8);
        float4 va = vrow[0], vb = vrow[1];
        u64 vv[8];
        vv[0] = pk2(va.x, va.x); vv[1] = pk2(va.y, va.y);
        vv[2] = pk2(va.z, va.z); vv[3] = pk2(va.w, va.w);
        vv[4] = pk2(vb.x, vb.x); vv[5] = pk2(vb.y, vb.y);
        vv[6] = pk2(vb.z, vb.z); vv[7] = pk2(vb.w, vb.w);
        const double2* wrow = reinterpret_cast<const double2*>(dyn + OFF_W + kk * 128 + tog * 8);
        double2 wa = wrow[0], wb = wrow[1];
        u64 wp[4] = {__double_as_longlong(wa.x), __double_as_longlong(wa.y),
                     __double_as_longlong(wb.x), __double_as_longlong(wb.y)};
#pragma unroll
        for (int j = 0; j < 8; j++) {
#pragma unroll
            for (int p = 0; p < 4; p++) fma2(acc[j * 4 + p], vv[j], wp[p]);
        }
    }
    __syncthreads();  // all sv (V) reads done; sv becomes S

    // ---- nonlinear: og<8 -> phi partials; og>=8 -> s into S(sv) ----
    int jb = tjg * 8;
    if (tog < 8) {
        int ob = tog * 8;
#pragma unroll
        for (int j = 0; j < 8; j++) {
            float ph = 0.f;
#pragma unroll
            for (int p = 0; p < 4; p++) {
                float2 f = upk2(acc[j * 4 + p]);
                ph += silu_f(f.x + dyn[OFF_BC + ob + 2 * p]) * dyn[OFF_CW2 + ob + 2 * p];
                ph += silu_f(f.y + dyn[OFF_BC + ob + 2 * p + 1]) * dyn[OFF_CW2 + ob + 2 * p + 1];
            }
            atomicAdd(&dyn[OFF_PHI + jb + j], ph);
        }
    } else {
        int ob = (tog - 8) * 8;
#pragma unroll
        for (int j = 0; j < 8; j++) {
            float wj = dyn[OFF_WJ + jb + j];
#pragma unroll
            for (int p = 0; p < 4; p++) {
                float2 f = upk2(acc[j * 4 + p]);
                sv[(ob + 2 * p) * SVR + jb + j] =
                    silu_f(wj * (f.x + dyn[OFF_BF + ob + 2 * p]) + dyn[OFF_FB1 + ob + 2 * p]);
                sv[(ob + 2 * p + 1) * SVR + jb + j] =
                    silu_f(wj * (f.y + dyn[OFF_BF + ob + 2 * p + 1]) + dyn[OFF_FB1 + ob + 2 * p + 1]);
            }
        }
    }
    __syncthreads();

    // ---- GEMM2: coeff[128j x 32c] = S[128x64] @ fw2[64x32]; 2 threads/j split-K ----
    int j2 = tid >> 1, ksel = tid & 1;
    u64 cacc[16];
#pragma unroll
    for (int t = 0; t < 16; t++)
        cacc[t] = ksel ? 0ull : pk2(dyn[OFF_FB2 + 2 * t], dyn[OFF_FB2 + 2 * t + 1]);
    {
        int k0 = ksel * 32;
#pragma unroll 8
        for (int kk = 0; kk < 32; kk++) {
            float s = sv[(k0 + kk) * SVR + j2];
            u64 s2 = pk2(s, s);
            const double2* wr = reinterpret_cast<const double2*>(dyn + OFF_F2 + (k0 + kk) * 32);
#pragma unroll
            for (int t = 0; t < 8; t++) {
                double2 q = wr[t];
                fma2(cacc[2 * t], s2, __double_as_longlong(q.x));
                fma2(cacc[2 * t + 1], s2, __double_as_longlong(q.y));
            }
        }
    }
    __syncthreads();  // all S reads done; sv rows 0..31 become coeff stage
    if (ksel == 0) {
#pragma unroll
        for (int t = 0; t < 16; t++) {
            float2 f = upk2(cacc[t]);
            sv[(2 * t) * SVR + j2] = f.x;
            sv[(2 * t + 1) * SVR + j2] = f.y;
        }
    }
    __syncthreads();
    if (ksel == 1) {
#pragma unroll
        for (int t = 0; t < 16; t++) {
            float2 f = upk2(cacc[t]);
            sv[(2 * t) * SVR + j2] += f.x;
            sv[(2 * t + 1) * SVR + j2] += f.y;
        }
    }
    __syncthreads();

    // ---- combos + x accumulators ----
    if (tid < 96) {
        int c = tid & 31, d = tid >> 5;
        const float* cp = sv + c * SVR;
        const float* dp = dyn + OFF_DIR + d * 128;
        float sacc = 0.f;
#pragma unroll 8
        for (int jj = 0; jj < 128; jj++) sacc += cp[jj] * dp[jj];
        atomicAdd(&g_combos[i * 96 + c * 3 + d], sacc);
    } else if (tid < 99) {
        int d = tid - 96;
        const float* dp = dyn + OFF_DXR + d * 128;
        const float* pp = dyn + OFF_PHI;
        float sacc = 0.f;
#pragma unroll 8
        for (int jj = 0; jj < 128; jj++) sacc += dp[jj] * pp[jj];
        atomicAdd(&g_xacc[i * 3 + d], sacc);
    }
}

// ---------------- K6: node-level MLPs + outputs -----------------------------------
__global__ void k_final(const float* __restrict__ h, const float* __restrict__ x,
                        const float* __restrict__ ew2, const float* __restrict__ eb2,
                        const float* __restrict__ nw1, const float* __restrict__ nb1,
                        const float* __restrict__ nw2, const float* __restrict__ nb2,
                        const float* __restrict__ pw1, const float* __restrict__ pb1,
                        const float* __restrict__ pw2, const float* __restrict__ pb2,
                        float* __restrict__ out, int write_x) {
    __shared__ float sq[32], p1[64], nin[192], n1[64], scv[64];
    int i = blockIdx.x, tid = threadIdx.x;
    scv[tid] = g_cv[i * 64 + tid];
    if (tid < 32) {
        float s = 0.f;
#pragma unroll
        for (int d = 0; d < 3; d++) {
            float cvv = g_combos[i * 96 + tid * 3 + d] * (1.f / 1024.f);
            s += cvv * cvv;
        }
        sq[tid] = s;
    }
    __syncthreads();
    {
        float a = g_wsum[i] * eb2[tid];
#pragma unroll 8
        for (int m = 0; m < 64; m++) a += scv[m] * ew2[m * 64 + tid];
        nin[64 + tid] = a;
        float b = pb1[tid];
#pragma unroll
        for (int c = 0; c < 32; c++) b += sq[c] * pw1[c * 64 + tid];
        p1[tid] = silu_f(b);
        nin[tid] = h[i * 64 + tid];
    }
    __syncthreads();
    {
        float a = pb2[tid];
#pragma unroll 8
        for (int m = 0; m < 64; m++) a += p1[m] * pw2[m * 64 + tid];
        nin[128 + tid] = a;
    }
    __syncthreads();
    {
        float a = nb1[tid];
#pragma unroll 8
        for (int m = 0; m < 192; m++) a += nin[m] * nw1[m * 64 + tid];
        n1[tid] = silu_f(a);
    }
    __syncthreads();
    {
        float a = nb2[tid];
#pragma unroll 8
        for (int m = 0; m < 64; m++) a += n1[m] * nw2[m * 64 + tid];
        out[i * 64 + tid] = h[i * 64 + tid] + a;
    }
    if (write_x && tid < 3)
        out[NN * 64 + i * 3 + tid] = x[i * 3 + tid] + g_xacc[i * 3 + tid] * (1.f / 1024.f);
}

// ---------------- host -------------------------------------------------------------
extern "C" void kernel_launch(void* const* d_in, const int* in_sizes, int n_in,
                              void* d_out, int out_size) {
    const float* h = (const float*)d_in[0];
    const float* x = (const float*)d_in[1];
    const float* ew1 = (const float*)d_in[2];
    const float* eb1 = (const float*)d_in[3];
    const float* ew2 = (const float*)d_in[4];
    const float* eb2 = (const float*)d_in[5];
    const float* nw1 = (const float*)d_in[6];
    const float* nb1 = (const float*)d_in[7];
    const float* nw2 = (const float*)d_in[8];
    const float* nb2 = (const float*)d_in[9];
    const float* cw1 = (const float*)d_in[10];
    const float* cb1 = (const float*)d_in[11];
    const float* cw2 = (const float*)d_in[12];
    const float* aw = (const float*)d_in[13];
    const float* ab = (const float*)d_in[14];
    const float* fw1 = (const float*)d_in[15];
    const float* fb1 = (const float*)d_in[16];
    const float* fw2 = (const float*)d_in[17];
    const float* fb2 = (const float*)d_in[18];
    const float* pw1 = (const float*)d_in[19];
    const float* pb1 = (const float*)d_in[20];
    const float* pw2 = (const float*)d_in[21];
    const float* pb2 = (const float*)d_in[22];
    const float* lg = (const float*)d_in[23];
    float* out = (float*)d_out;

    const int K4_SMEM = K4_FLOATS * sizeof(float);  // 81552 B
    cudaFuncSetAttribute(k_pair, cudaFuncAttributeMaxDynamicSharedMemorySize, K4_SMEM);

    int write_x = (out_size >= NN * 64 + NN * 3) ? 1 : 0;

    k_zero<<<(NN * 96 + 255) / 256, 256>>>();
    k_fold<<<65, 64>>>(ew1, ew2, eb2, cw1, cb1, fw1, aw, ab);
    k_node_pre<<<NN, 64>>>(h, ew1, eb1);
    k_edge1<<<dim3(NN / 256, NN), 256>>>(x);
    k_attn<<<NN, 256>>>(x, lg);
    k_pair<<<dim3(NN / 128, NN), 256, K4_SMEM>>>(x, fw2, fb1, fb2, cw2);
    k_final<<<NN, 64>>>(h, x, ew2, eb2, nw1, nb1, nw2, nb2, pw1, pb1, pw2, pb2, out, write_x);
}

// round 8
// speedup vs baseline: 1.8166x; 1.8166x over previous
#include <cuda_runtime.h>
#include <cuda_fp16.h>

#define NN 1024
#define EPSF 1e-5f
#define INFF 1e5f

typedef unsigned long long u64;
typedef unsigned int u32;

// ---------------- device scratch --------------------------------------------------
__device__ float g_A[NN * 64];                  // h@ew1[0:64] + eb1
__device__ float g_Bt[64 * NN];                 // h@ew1[64:128], k-major [k][j]
__device__ float g_slog[NN * NN];
__device__ float g_w[NN * NN];
__device__ float g_wsum[NN];
__device__ float g_cv[NN * 64];
__device__ float g_combos[NN * 96];
__device__ float g_xacc[NN * 3];
// folded weights
__device__ __half g_Wh[64 * 128];               // fp16, row k: [ew2@cw1 | ew2@fw1]
__device__ float g_bc[64];                      // eb2@cw1 + cb1
__device__ float g_bf1a[64];                    // eb2@fw1
__device__ float g_waw[64];                     // ew2@aw
__device__ float g_baw[1];                      // eb2.aw + ab
__device__ float g_Cw[64];                      // ew1 row 128

// ---------------- helpers ---------------------------------------------------------
__device__ __forceinline__ __half2 u2h2(u32 u) {
    __half2 h;
    *reinterpret_cast<u32*>(&h) = u;
    return h;
}
__device__ __forceinline__ float silu_f(float v) {
    return __fdividef(v, 1.f + __expf(-v));
}

__device__ __forceinline__ float blk_red(float v, float* red, int tid, bool ismax) {
    red[tid] = v;
    __syncthreads();
#pragma unroll
    for (int s = 128; s >= 1; s >>= 1) {
        if (tid < s) red[tid] = ismax ? fmaxf(red[tid], red[tid + s]) : red[tid] + red[tid + s];
        __syncthreads();
    }
    float r = red[0];
    __syncthreads();
    return r;
}

// ---------------- K-zero ----------------------------------------------------------
__global__ void k_zero() {
    int idx = blockIdx.x * blockDim.x + threadIdx.x;
    if (idx < NN * 64) g_cv[idx] = 0.f;
    if (idx < NN * 96) g_combos[idx] = 0.f;
    if (idx < NN * 3) g_xacc[idx] = 0.f;
}

// ---------------- k_fold ----------------------------------------------------------
__global__ void k_fold(const float* __restrict__ ew1, const float* __restrict__ ew2,
                       const float* __restrict__ eb2, const float* __restrict__ cw1,
                       const float* __restrict__ cb1, const float* __restrict__ fw1,
                       const float* __restrict__ aw, const float* __restrict__ ab) {
    int b = blockIdx.x, tid = threadIdx.x;  // 64 threads
    if (b < 64) {
        __shared__ float se[64];
        se[tid] = ew2[b * 64 + tid];
        __syncthreads();
        float ac = 0.f, af = 0.f;
#pragma unroll 8
        for (int k = 0; k < 64; k++) {
            float e = se[k];
            ac += e * cw1[k * 64 + tid];
            af += e * fw1[k * 64 + tid];
        }
        g_Wh[b * 128 + tid] = __float2half(ac);
        g_Wh[b * 128 + 64 + tid] = __float2half(af);
    } else {
        float sw = 0.f;
        for (int k = 0; k < 64; k++) sw += ew2[tid * 64 + k] * aw[k];
        g_waw[tid] = sw;
        float bc = cb1[tid], bf = 0.f;
        for (int k = 0; k < 64; k++) {
            bc += eb2[k] * cw1[k * 64 + tid];
            bf += eb2[k] * fw1[k * 64 + tid];
        }
        g_bc[tid] = bc;
        g_bf1a[tid] = bf;
        g_Cw[tid] = ew1[128 * 64 + tid];
        if (tid == 0) {
            float s = ab[0];
            for (int k = 0; k < 64; k++) s += eb2[k] * aw[k];
            g_baw[0] = s;
        }
    }
}

// ---------------- K0: per-node first-layer GEMVs ----------------------------------
__global__ void k_node_pre(const float* __restrict__ h, const float* __restrict__ ew1,
                           const float* __restrict__ eb1) {
    __shared__ float hr[64];
    int i = blockIdx.x, tid = threadIdx.x;
    hr[tid] = h[i * 64 + tid];
    __syncthreads();
    float a = eb1[tid], b = 0.f;
#pragma unroll 8
    for (int m = 0; m < 64; m++) {
        float hm = hr[m];
        a += hm * ew1[m * 64 + tid];
        b += hm * ew1[(64 + m) * 64 + tid];
    }
    g_A[i * 64 + tid] = a;
    g_Bt[tid * NN + i] = b;
}

// ---------------- K1: semantic logits ---------------------------------------------
__global__ void __launch_bounds__(256) k_edge1(const float* __restrict__ x) {
    __shared__ float sA[64], sC[64], sW[64], sXi[3], sBaw[1];
    int i = blockIdx.y, tid = threadIdx.x;
    int j = blockIdx.x * 256 + tid;
    if (tid < 64) {
        sA[tid] = g_A[i * 64 + tid];
        sC[tid] = g_Cw[tid];
        sW[tid] = g_waw[tid];
    }
    if (tid < 3) sXi[tid] = x[i * 3 + tid];
    if (tid == 0) sBaw[0] = g_baw[0];
    __syncthreads();

    float dx = sXi[0] - x[j * 3 + 0];
    float dy = sXi[1] - x[j * 3 + 1];
    float dz = sXi[2] - x[j * 3 + 2];
    float nrm = sqrtf(dx * dx + dy * dy + dz * dz + EPSF);

    float slog = sBaw[0];
#pragma unroll 8
    for (int k = 0; k < 64; k++) {
        float b = g_Bt[k * NN + j];
        slog += silu_f(sA[k] + b + nrm * sC[k]) * sW[k];
    }
    slog = (slog > 0.f) ? slog : 0.01f * slog;
    g_slog[i * NN + j] = slog;
}

// ---------------- K3: fused softmax combine ---------------------------------------
__global__ void k_attn(const float* __restrict__ x, const float* __restrict__ lg) {
    __shared__ float sls[NN], sle[NN];
    __shared__ float red[256];
    int i = blockIdx.x, tid = threadIdx.x;
    float gamma = __expf(lg[0]);
    float xi0 = x[i * 3 + 0], xi1 = x[i * 3 + 1], xi2 = x[i * 3 + 2];

    for (int j = tid; j < NN; j += 256) {
        float dx = xi0 - x[j * 3 + 0];
        float dy = xi1 - x[j * 3 + 1];
        float dz = xi2 - x[j * 3 + 2];
        float nrm = sqrtf(dx * dx + dy * dy + dz * dz + EPSF);
        float diag = (j == i) ? INFF : 0.f;
        sle[j] = -(nrm + diag) * gamma;
        sls[j] = g_slog[i * NN + j] - diag;
    }
    __syncthreads();

    float m = -3.4e38f;
    for (int j = tid; j < NN; j += 256) m = fmaxf(m, sls[j]);
    m = blk_red(m, red, tid, true);

    float ze = 0.f, zs = 0.f, tt = 0.f;
    for (int j = tid; j < NN; j += 256) {
        float le = sle[j], ls = sls[j] - m;
        ze += __expf(le);
        zs += __expf(ls);
        tt += __expf(le + ls);
    }
    ze = blk_red(ze, red, tid, false);
    zs = blk_red(zs, red, tid, false);
    tt = blk_red(tt, red, tid, false);

    float inv = 1.f / (tt + EPSF * ze * zs);
    for (int j = tid; j < NN; j += 256)
        g_w[i * NN + j] = __expf(sle[j] + sls[j] - m) * inv;
    if (tid == 0) g_wsum[i] = tt * inv;
}

// ---------------- K4: fused pair kernel (fp16 GEMMs) ------------------------------
// smem float offsets
#define OFF_SV   0          // 64 x 261 fp32 (reused as staging rows 0..38 at end)
#define SVS      261
#define OFF_WH   16704      // 8192 halfs = 4096 floats
#define OFF_F2H  20800      // 2048 halfs = 1024 floats
#define OFF_SWT  21824      // 256
#define OFF_BC   22080
#define OFF_BF   22144
#define OFF_FB1  22208
#define OFF_CW2  22272
#define OFF_A    22336
#define OFF_C    22400
#define OFF_FB2  22464      // 32
#define OFF_XI   22496      // 4
#define OFF_CVP  22500      // 64 x 4
#define K4_FLOATS 22756

__global__ void __launch_bounds__(256, 2) k_pair(const float* __restrict__ x,
                                                 const float* __restrict__ fw2,
                                                 const float* __restrict__ fb1,
                                                 const float* __restrict__ fb2,
                                                 const float* __restrict__ cw2) {
    extern __shared__ __align__(16) float dyn[];
    float* sv = dyn + OFF_SV;
    __half* sWh = reinterpret_cast<__half*>(dyn + OFF_WH);
    __half* sF2h = reinterpret_cast<__half*>(dyn + OFF_F2H);
    float* swt = dyn + OFF_SWT;

    int i = blockIdx.y, tid = threadIdx.x;
    int j = blockIdx.x * 256 + tid;

    {
        const u32* gW = reinterpret_cast<const u32*>(g_Wh);
        u32* sW = reinterpret_cast<u32*>(sWh);
        for (int t = tid; t < 4096; t += 256) sW[t] = gW[t];
    }
    for (int t = tid; t < 2048; t += 256) sF2h[t] = __float2half(fw2[t]);
    if (tid < 64) {
        dyn[OFF_BC + tid] = g_bc[tid];
        dyn[OFF_BF + tid] = g_bf1a[tid];
        dyn[OFF_FB1 + tid] = fb1[tid];
        dyn[OFF_CW2 + tid] = cw2[tid];
        dyn[OFF_A + tid] = g_A[i * 64 + tid];
        dyn[OFF_C + tid] = g_Cw[tid];
    }
    if (tid < 32) dyn[OFF_FB2 + tid] = fb2[tid];
    if (tid < 3) dyn[OFF_XI + tid] = x[i * 3 + tid];
    __syncthreads();

    // ---- phase A: geometry + v (fp32 -> sv) ----
    float dxr0 = dyn[OFF_XI + 0] - x[j * 3 + 0];
    float dxr1 = dyn[OFF_XI + 1] - x[j * 3 + 1];
    float dxr2 = dyn[OFF_XI + 2] - x[j * 3 + 2];
    float nrm = sqrtf(dxr0 * dxr0 + dxr1 * dxr1 + dxr2 * dxr2 + EPSF);
    float inv1 = __fdividef(1.f, nrm + 1.f);
    float w = g_w[i * NN + j];
    swt[tid] = w;

#pragma unroll 8
    for (int k = 0; k < 64; k++) {
        float b = g_Bt[k * NN + j];
        sv[k * SVS + tid] = silu_f(dyn[OFF_A + k] + b + nrm * dyn[OFF_C + k]);
    }

    // ---- phase B: fused fp16 Wc/Wf1 GEMVs + second layers ----
    float phi = 0.f;
    __half2 cacc[16];
    const __half2 hz = __float2half2_rn(0.f);
#pragma unroll
    for (int t = 0; t < 16; t++) cacc[t] = hz;

    for (int q = 0; q < 4; q++) {
        __half2 tqc[8], tqf[8];
#pragma unroll
        for (int t = 0; t < 8; t++) { tqc[t] = hz; tqf[t] = hz; }
#pragma unroll 8
        for (int kk = 0; kk < 64; kk++) {
            __half2 v2 = __float2half2_rn(sv[kk * SVS + tid]);
            const uint4* pc = reinterpret_cast<const uint4*>(sWh + kk * 128 + q * 16);
            const uint4* pf = reinterpret_cast<const uint4*>(sWh + kk * 128 + 64 + q * 16);
            uint4 wa = pc[0], wb = pc[1];
            uint4 fa = pf[0], fb = pf[1];
            tqc[0] = __hfma2(v2, u2h2(wa.x), tqc[0]);
            tqc[1] = __hfma2(v2, u2h2(wa.y), tqc[1]);
            tqc[2] = __hfma2(v2, u2h2(wa.z), tqc[2]);
            tqc[3] = __hfma2(v2, u2h2(wa.w), tqc[3]);
            tqc[4] = __hfma2(v2, u2h2(wb.x), tqc[4]);
            tqc[5] = __hfma2(v2, u2h2(wb.y), tqc[5]);
            tqc[6] = __hfma2(v2, u2h2(wb.z), tqc[6]);
            tqc[7] = __hfma2(v2, u2h2(wb.w), tqc[7]);
            tqf[0] = __hfma2(v2, u2h2(fa.x), tqf[0]);
            tqf[1] = __hfma2(v2, u2h2(fa.y), tqf[1]);
            tqf[2] = __hfma2(v2, u2h2(fa.z), tqf[2]);
            tqf[3] = __hfma2(v2, u2h2(fa.w), tqf[3]);
            tqf[4] = __hfma2(v2, u2h2(fb.x), tqf[4]);
            tqf[5] = __hfma2(v2, u2h2(fb.y), tqf[5]);
            tqf[6] = __hfma2(v2, u2h2(fb.z), tqf[6]);
            tqf[7] = __hfma2(v2, u2h2(fb.w), tqf[7]);
        }
        float s[16];
#pragma unroll
        for (int t = 0; t < 8; t++) {
            float2 fc = __half22float2(tqc[t]);
            phi += silu_f(fc.x + dyn[OFF_BC + q * 16 + 2 * t]) * dyn[OFF_CW2 + q * 16 + 2 * t];
            phi += silu_f(fc.y + dyn[OFF_BC + q * 16 + 2 * t + 1]) * dyn[OFF_CW2 + q * 16 + 2 * t + 1];
            float2 ff = __half22float2(tqf[t]);
            s[2 * t] = silu_f(w * (ff.x + dyn[OFF_BF + q * 16 + 2 * t]) + dyn[OFF_FB1 + q * 16 + 2 * t]);
            s[2 * t + 1] = silu_f(w * (ff.y + dyn[OFF_BF + q * 16 + 2 * t + 1]) + dyn[OFF_FB1 + q * 16 + 2 * t + 1]);
        }
        // cacc += s @ fw2[q*16 : q*16+16, :]   (fp16)
#pragma unroll
        for (int kk = 0; kk < 16; kk++) {
            __half2 s2 = __float2half2_rn(s[kk]);
            const uint4* wr = reinterpret_cast<const uint4*>(sF2h + (q * 16 + kk) * 32);
            uint4 a0 = wr[0], a1 = wr[1], a2 = wr[2], a3 = wr[3];
            cacc[0] = __hfma2(s2, u2h2(a0.x), cacc[0]);
            cacc[1] = __hfma2(s2, u2h2(a0.y), cacc[1]);
            cacc[2] = __hfma2(s2, u2h2(a0.z), cacc[2]);
            cacc[3] = __hfma2(s2, u2h2(a0.w), cacc[3]);
            cacc[4] = __hfma2(s2, u2h2(a1.x), cacc[4]);
            cacc[5] = __hfma2(s2, u2h2(a1.y), cacc[5]);
            cacc[6] = __hfma2(s2, u2h2(a1.z), cacc[6]);
            cacc[7] = __hfma2(s2, u2h2(a1.w), cacc[7]);
            cacc[8] = __hfma2(s2, u2h2(a2.x), cacc[8]);
            cacc[9] = __hfma2(s2, u2h2(a2.y), cacc[9]);
            cacc[10] = __hfma2(s2, u2h2(a2.z), cacc[10]);
            cacc[11] = __hfma2(s2, u2h2(a2.w), cacc[11]);
            cacc[12] = __hfma2(s2, u2h2(a3.x), cacc[12]);
            cacc[13] = __hfma2(s2, u2h2(a3.y), cacc[13]);
            cacc[14] = __hfma2(s2, u2h2(a3.z), cacc[14]);
            cacc[15] = __hfma2(s2, u2h2(a3.w), cacc[15]);
        }
    }
    float coeff[32];
#pragma unroll
    for (int t = 0; t < 16; t++) {
        float2 f = __half22float2(cacc[t]);
        coeff[2 * t] = f.x + dyn[OFF_FB2 + 2 * t];
        coeff[2 * t + 1] = f.y + dyn[OFF_FB2 + 2 * t + 1];
    }

    // ---- epilogue 1: cv = sum_j w*v  (parallel column reduce) ----
    __syncthreads();
    {
        int k = tid & 63, qq = tid >> 6;
        const float* vp = sv + k * SVS + qq * 64;
        const float* wp = swt + qq * 64;
        float sacc = 0.f;
#pragma unroll 8
        for (int jj = 0; jj < 64; jj++) sacc += wp[jj] * vp[jj];
        dyn[OFF_CVP + k * 4 + qq] = sacc;
    }
    __syncthreads();
    if (tid < 64) {
        const float4 p = *reinterpret_cast<const float4*>(dyn + OFF_CVP + tid * 4);
        atomicAdd(&g_cv[i * 64 + tid], p.x + p.y + p.z + p.w);
    }

    // ---- epilogue 2: stage coeff/dir/dxr/phi into sv region ----
    __syncthreads();
#pragma unroll
    for (int c = 0; c < 32; c++) sv[c * SVS + tid] = coeff[c];
    sv[32 * SVS + tid] = dxr0 * inv1;
    sv[33 * SVS + tid] = dxr1 * inv1;
    sv[34 * SVS + tid] = dxr2 * inv1;
    sv[35 * SVS + tid] = dxr0;
    sv[36 * SVS + tid] = dxr1;
    sv[37 * SVS + tid] = dxr2;
    sv[38 * SVS + tid] = phi;
    __syncthreads();

    if (tid < 96) {
        int c = tid / 3, d = tid % 3;
        const float* cp = sv + c * SVS;
        const float* dp = sv + (32 + d) * SVS;
        float sacc = 0.f;
#pragma unroll 8
        for (int jj = 0; jj < 256; jj++) sacc += cp[jj] * dp[jj];
        atomicAdd(&g_combos[i * 96 + c * 3 + d], sacc);
    } else if (tid < 99) {
        int d = tid - 96;
        const float* dp = sv + (35 + d) * SVS;
        const float* pp = sv + 38 * SVS;
        float sacc = 0.f;
#pragma unroll 8
        for (int jj = 0; jj < 256; jj++) sacc += dp[jj] * pp[jj];
        atomicAdd(&g_xacc[i * 3 + d], sacc);
    }
}

// ---------------- K6: node-level MLPs + outputs -----------------------------------
__global__ void k_final(const float* __restrict__ h, const float* __restrict__ x,
                        const float* __restrict__ ew2, const float* __restrict__ eb2,
                        const float* __restrict__ nw1, const float* __restrict__ nb1,
                        const float* __restrict__ nw2, const float* __restrict__ nb2,
                        const float* __restrict__ pw1, const float* __restrict__ pb1,
                        const float* __restrict__ pw2, const float* __restrict__ pb2,
                        float* __restrict__ out, int write_x) {
    __shared__ float sq[32], p1[64], nin[192], n1[64], scv[64];
    int i = blockIdx.x, tid = threadIdx.x;
    scv[tid] = g_cv[i * 64 + tid];
    if (tid < 32) {
        float s = 0.f;
#pragma unroll
        for (int d = 0; d < 3; d++) {
            float cvv = g_combos[i * 96 + tid * 3 + d] * (1.f / 1024.f);
            s += cvv * cvv;
        }
        sq[tid] = s;
    }
    __syncthreads();
    {
        float a = g_wsum[i] * eb2[tid];
#pragma unroll 8
        for (int m = 0; m < 64; m++) a += scv[m] * ew2[m * 64 + tid];
        nin[64 + tid] = a;
        float b = pb1[tid];
#pragma unroll
        for (int c = 0; c < 32; c++) b += sq[c] * pw1[c * 64 + tid];
        p1[tid] = silu_f(b);
        nin[tid] = h[i * 64 + tid];
    }
    __syncthreads();
    {
        float a = pb2[tid];
#pragma unroll 8
        for (int m = 0; m < 64; m++) a += p1[m] * pw2[m * 64 + tid];
        nin[128 + tid] = a;
    }
    __syncthreads();
    {
        float a = nb1[tid];
#pragma unroll 8
        for (int m = 0; m < 192; m++) a += nin[m] * nw1[m * 64 + tid];
        n1[tid] = silu_f(a);
    }
    __syncthreads();
    {
        float a = nb2[tid];
#pragma unroll 8
        for (int m = 0; m < 64; m++) a += n1[m] * nw2[m * 64 + tid];
        out[i * 64 + tid] = h[i * 64 + tid] + a;
    }
    if (write_x && tid < 3)
        out[NN * 64 + i * 3 + tid] = x[i * 3 + tid] + g_xacc[i * 3 + tid] * (1.f / 1024.f);
}

// ---------------- host -------------------------------------------------------------
extern "C" void kernel_launch(void* const* d_in, const int* in_sizes, int n_in,
                              void* d_out, int out_size) {
    const float* h = (const float*)d_in[0];
    const float* x = (const float*)d_in[1];
    const float* ew1 = (const float*)d_in[2];
    const float* eb1 = (const float*)d_in[3];
    const float* ew2 = (const float*)d_in[4];
    const float* eb2 = (const float*)d_in[5];
    const float* nw1 = (const float*)d_in[6];
    const float* nb1 = (const float*)d_in[7];
    const float* nw2 = (const float*)d_in[8];
    const float* nb2 = (const float*)d_in[9];
    const float* cw1 = (const float*)d_in[10];
    const float* cb1 = (const float*)d_in[11];
    const float* cw2 = (const float*)d_in[12];
    const float* aw = (const float*)d_in[13];
    const float* ab = (const float*)d_in[14];
    const float* fw1 = (const float*)d_in[15];
    const float* fb1 = (const float*)d_in[16];
    const float* fw2 = (const float*)d_in[17];
    const float* fb2 = (const float*)d_in[18];
    const float* pw1 = (const float*)d_in[19];
    const float* pb1 = (const float*)d_in[20];
    const float* pw2 = (const float*)d_in[21];
    const float* pb2 = (const float*)d_in[22];
    const float* lg = (const float*)d_in[23];
    float* out = (float*)d_out;

    const int K4_SMEM = K4_FLOATS * sizeof(float);  // 91024 B
    cudaFuncSetAttribute(k_pair, cudaFuncAttributeMaxDynamicSharedMemorySize, K4_SMEM);

    int write_x = (out_size >= NN * 64 + NN * 3) ? 1 : 0;

    k_zero<<<(NN * 96 + 255) / 256, 256>>>();
    k_fold<<<65, 64>>>(ew1, ew2, eb2, cw1, cb1, fw1, aw, ab);
    k_node_pre<<<NN, 64>>>(h, ew1, eb1);
    k_edge1<<<dim3(NN / 256, NN), 256>>>(x);
    k_attn<<<NN, 256>>>(x, lg);
    k_pair<<<dim3(NN / 256, NN), 256, K4_SMEM>>>(x, fw2, fb1, fb2, cw2);
    k_final<<<NN, 64>>>(h, x, ew2, eb2, nw1, nb1, nw2, nb2, pw1, pb1, pw2, pb2, out, write_x);
}

// round 9
// speedup vs baseline: 1.8571x; 1.0223x over previous
#include <cuda_runtime.h>
#include <cuda_fp16.h>

#define NN 1024
#define EPSF 1e-5f
#define INFF 1e5f

typedef unsigned long long u64;
typedef unsigned int u32;

// ---------------- device scratch --------------------------------------------------
__device__ float g_A[NN * 64];                  // h@ew1[0:64] + eb1
__device__ float g_Bt[64 * NN];                 // h@ew1[64:128], k-major [k][j]
__device__ float g_slog[NN * NN];
__device__ float g_w[NN * NN];
__device__ float g_wsum[NN];
__device__ float g_cv[NN * 64];
__device__ float g_M[NN * 192];                 // M[i][k][d] = sum_j S * dir
__device__ float g_Dsum[NN * 3];
__device__ float g_xacc[NN * 3];
// folded weights
__device__ __half g_Wh[64 * 128];               // fp16, row k: [ew2@cw1 | ew2@fw1]
__device__ float g_bc[64];                      // eb2@cw1 + cb1
__device__ float g_bf1a[64];                    // eb2@fw1
__device__ float g_waw[64];                     // ew2@aw
__device__ float g_baw[1];                      // eb2.aw + ab
__device__ float g_Cw[64];                      // ew1 row 128

// ---------------- helpers ---------------------------------------------------------
__device__ __forceinline__ __half2 u2h2(u32 u) {
    __half2 h;
    *reinterpret_cast<u32*>(&h) = u;
    return h;
}
__device__ __forceinline__ float silu_f(float v) {
    return __fdividef(v, 1.f + __expf(-v));
}

__device__ __forceinline__ float blk_red(float v, float* red, int tid, bool ismax) {
    red[tid] = v;
    __syncthreads();
#pragma unroll
    for (int s = 128; s >= 1; s >>= 1) {
        if (tid < s) red[tid] = ismax ? fmaxf(red[tid], red[tid + s]) : red[tid] + red[tid + s];
        __syncthreads();
    }
    float r = red[0];
    __syncthreads();
    return r;
}

// ---------------- K-zero ----------------------------------------------------------
__global__ void k_zero() {
    int idx = blockIdx.x * blockDim.x + threadIdx.x;
    if (idx < NN * 64) g_cv[idx] = 0.f;
    if (idx < NN * 192) g_M[idx] = 0.f;
    if (idx < NN * 3) { g_xacc[idx] = 0.f; g_Dsum[idx] = 0.f; }
}

// ---------------- k_fold ----------------------------------------------------------
__global__ void k_fold(const float* __restrict__ ew1, const float* __restrict__ ew2,
                       const float* __restrict__ eb2, const float* __restrict__ cw1,
                       const float* __restrict__ cb1, const float* __restrict__ fw1,
                       const float* __restrict__ aw, const float* __restrict__ ab) {
    int b = blockIdx.x, tid = threadIdx.x;  // 64 threads
    if (b < 64) {
        __shared__ float se[64];
        se[tid] = ew2[b * 64 + tid];
        __syncthreads();
        float ac = 0.f, af = 0.f;
#pragma unroll 8
        for (int k = 0; k < 64; k++) {
            float e = se[k];
            ac += e * cw1[k * 64 + tid];
            af += e * fw1[k * 64 + tid];
        }
        g_Wh[b * 128 + tid] = __float2half(ac);
        g_Wh[b * 128 + 64 + tid] = __float2half(af);
    } else {
        float sw = 0.f;
        for (int k = 0; k < 64; k++) sw += ew2[tid * 64 + k] * aw[k];
        g_waw[tid] = sw;
        float bc = cb1[tid], bf = 0.f;
        for (int k = 0; k < 64; k++) {
            bc += eb2[k] * cw1[k * 64 + tid];
            bf += eb2[k] * fw1[k * 64 + tid];
        }
        g_bc[tid] = bc;
        g_bf1a[tid] = bf;
        g_Cw[tid] = ew1[128 * 64 + tid];
        if (tid == 0) {
            float s = ab[0];
            for (int k = 0; k < 64; k++) s += eb2[k] * aw[k];
            g_baw[0] = s;
        }
    }
}

// ---------------- K0: per-node first-layer GEMVs ----------------------------------
__global__ void k_node_pre(const float* __restrict__ h, const float* __restrict__ ew1,
                           const float* __restrict__ eb1) {
    __shared__ float hr[64];
    int i = blockIdx.x, tid = threadIdx.x;
    hr[tid] = h[i * 64 + tid];
    __syncthreads();
    float a = eb1[tid], b = 0.f;
#pragma unroll 8
    for (int m = 0; m < 64; m++) {
        float hm = hr[m];
        a += hm * ew1[m * 64 + tid];
        b += hm * ew1[(64 + m) * 64 + tid];
    }
    g_A[i * 64 + tid] = a;
    g_Bt[tid * NN + i] = b;
}

// ---------------- K1: semantic logits ---------------------------------------------
__global__ void __launch_bounds__(256) k_edge1(const float* __restrict__ x) {
    __shared__ float sA[64], sC[64], sW[64], sXi[3], sBaw[1];
    int i = blockIdx.y, tid = threadIdx.x;
    int j = blockIdx.x * 256 + tid;
    if (tid < 64) {
        sA[tid] = g_A[i * 64 + tid];
        sC[tid] = g_Cw[tid];
        sW[tid] = g_waw[tid];
    }
    if (tid < 3) sXi[tid] = x[i * 3 + tid];
    if (tid == 0) sBaw[0] = g_baw[0];
    __syncthreads();

    float dx = sXi[0] - x[j * 3 + 0];
    float dy = sXi[1] - x[j * 3 + 1];
    float dz = sXi[2] - x[j * 3 + 2];
    float nrm = sqrtf(dx * dx + dy * dy + dz * dz + EPSF);

    float slog = sBaw[0];
#pragma unroll 8
    for (int k = 0; k < 64; k++) {
        float b = g_Bt[k * NN + j];
        slog += silu_f(sA[k] + b + nrm * sC[k]) * sW[k];
    }
    slog = (slog > 0.f) ? slog : 0.01f * slog;
    g_slog[i * NN + j] = slog;
}

// ---------------- K3: fused softmax combine ---------------------------------------
__global__ void k_attn(const float* __restrict__ x, const float* __restrict__ lg) {
    __shared__ float sls[NN], sle[NN];
    __shared__ float red[256];
    int i = blockIdx.x, tid = threadIdx.x;
    float gamma = __expf(lg[0]);
    float xi0 = x[i * 3 + 0], xi1 = x[i * 3 + 1], xi2 = x[i * 3 + 2];

    for (int j = tid; j < NN; j += 256) {
        float dx = xi0 - x[j * 3 + 0];
        float dy = xi1 - x[j * 3 + 1];
        float dz = xi2 - x[j * 3 + 2];
        float nrm = sqrtf(dx * dx + dy * dy + dz * dz + EPSF);
        float diag = (j == i) ? INFF : 0.f;
        sle[j] = -(nrm + diag) * gamma;
        sls[j] = g_slog[i * NN + j] - diag;
    }
    __syncthreads();

    float m = -3.4e38f;
    for (int j = tid; j < NN; j += 256) m = fmaxf(m, sls[j]);
    m = blk_red(m, red, tid, true);

    float ze = 0.f, zs = 0.f, tt = 0.f;
    for (int j = tid; j < NN; j += 256) {
        float le = sle[j], ls = sls[j] - m;
        ze += __expf(le);
        zs += __expf(ls);
        tt += __expf(le + ls);
    }
    ze = blk_red(ze, red, tid, false);
    zs = blk_red(zs, red, tid, false);
    tt = blk_red(tt, red, tid, false);

    float inv = 1.f / (tt + EPSF * ze * zs);
    for (int j = tid; j < NN; j += 256)
        g_w[i * NN + j] = __expf(sle[j] + sls[j] - m) * inv;
    if (tid == 0) g_wsum[i] = tt * inv;
}

// ---------------- K4: fused pair kernel (fp16 GEMM1, M-trick epilogue) ------------
// smem float offsets
#define OFF_SV   0          // 64 x 261 fp32: v, then S in-place (column-private)
#define SVS      261
#define OFF_WH   16704      // 8192 halfs = 4096 floats
#define OFF_SWT  20800      // 256 (w)
#define OFF_BC   21056
#define OFF_BF   21120
#define OFF_FB1  21184
#define OFF_CW2  21248
#define OFF_A    21312
#define OFF_C    21376
#define OFF_XI   21440      // 4
#define OFF_CVP  21444      // 256
#define OFF_DIR  21700      // 3 x 256
#define OFF_DXR  22468      // 3 x 256
#define OFF_PHI  23236      // 256
#define K4_FLOATS 23492

__global__ void __launch_bounds__(256, 2) k_pair(const float* __restrict__ x,
                                                 const float* __restrict__ fb1,
                                                 const float* __restrict__ cw2) {
    extern __shared__ __align__(16) float dyn[];
    float* sv = dyn + OFF_SV;
    __half* sWh = reinterpret_cast<__half*>(dyn + OFF_WH);
    float* swt = dyn + OFF_SWT;

    int i = blockIdx.y, tid = threadIdx.x;
    int j = blockIdx.x * 256 + tid;

    {
        const u32* gW = reinterpret_cast<const u32*>(g_Wh);
        u32* sW = reinterpret_cast<u32*>(sWh);
        for (int t = tid; t < 4096; t += 256) sW[t] = gW[t];
    }
    if (tid < 64) {
        dyn[OFF_BC + tid] = g_bc[tid];
        dyn[OFF_BF + tid] = g_bf1a[tid];
        dyn[OFF_FB1 + tid] = fb1[tid];
        dyn[OFF_CW2 + tid] = cw2[tid];
        dyn[OFF_A + tid] = g_A[i * 64 + tid];
        dyn[OFF_C + tid] = g_Cw[tid];
    }
    if (tid < 3) dyn[OFF_XI + tid] = x[i * 3 + tid];
    __syncthreads();

    // ---- phase A: geometry + v (fp32 -> sv) ----
    float dxr0 = dyn[OFF_XI + 0] - x[j * 3 + 0];
    float dxr1 = dyn[OFF_XI + 1] - x[j * 3 + 1];
    float dxr2 = dyn[OFF_XI + 2] - x[j * 3 + 2];
    float nrm = sqrtf(dxr0 * dxr0 + dxr1 * dxr1 + dxr2 * dxr2 + EPSF);
    float inv1 = __fdividef(1.f, nrm + 1.f);
    float w = g_w[i * NN + j];
    swt[tid] = w;
    dyn[OFF_DXR + 0 * 256 + tid] = dxr0;
    dyn[OFF_DXR + 1 * 256 + tid] = dxr1;
    dyn[OFF_DXR + 2 * 256 + tid] = dxr2;
    dyn[OFF_DIR + 0 * 256 + tid] = dxr0 * inv1;
    dyn[OFF_DIR + 1 * 256 + tid] = dxr1 * inv1;
    dyn[OFF_DIR + 2 * 256 + tid] = dxr2 * inv1;

#pragma unroll 8
    for (int k = 0; k < 64; k++) {
        float b = g_Bt[k * NN + j];
        sv[k * SVS + tid] = silu_f(dyn[OFF_A + k] + b + nrm * dyn[OFF_C + k]);
    }
    __syncthreads();

    // ---- cv = sum_j w*v (before GEMM so S can overwrite sv columns later) ----
    {
        int k = tid & 63, qq = tid >> 6;
        const float* vp = sv + k * SVS + qq * 64;
        const float* wp = swt + qq * 64;
        float sacc = 0.f;
#pragma unroll 8
        for (int jj = 0; jj < 64; jj++) sacc += wp[jj] * vp[jj];
        dyn[OFF_CVP + k * 4 + qq] = sacc;
    }
    __syncthreads();
    if (tid < 64) {
        const float4 p = *reinterpret_cast<const float4*>(dyn + OFF_CVP + tid * 4);
        atomicAdd(&g_cv[i * 64 + tid], p.x + p.y + p.z + p.w);
    }

    // ---- pass 1: Pc = v @ Wc (outputs 0..63) -> phi ----
    const __half2 hz = __float2half2_rn(0.f);
    {
        __half2 acc[32];
#pragma unroll
        for (int t = 0; t < 32; t++) acc[t] = hz;
#pragma unroll 4
        for (int kk = 0; kk < 64; kk++) {
            __half2 v2 = __float2half2_rn(sv[kk * SVS + tid]);
            const uint4* wr = reinterpret_cast<const uint4*>(sWh + kk * 128);
#pragma unroll
            for (int c = 0; c < 8; c++) {
                uint4 q = wr[c];
                acc[4 * c + 0] = __hfma2(v2, u2h2(q.x), acc[4 * c + 0]);
                acc[4 * c + 1] = __hfma2(v2, u2h2(q.y), acc[4 * c + 1]);
                acc[4 * c + 2] = __hfma2(v2, u2h2(q.z), acc[4 * c + 2]);
                acc[4 * c + 3] = __hfma2(v2, u2h2(q.w), acc[4 * c + 3]);
            }
        }
        float ph = 0.f;
#pragma unroll
        for (int t = 0; t < 32; t++) {
            float2 f = __half22float2(acc[t]);
            ph += silu_f(f.x + dyn[OFF_BC + 2 * t]) * dyn[OFF_CW2 + 2 * t];
            ph += silu_f(f.y + dyn[OFF_BC + 2 * t + 1]) * dyn[OFF_CW2 + 2 * t + 1];
        }
        dyn[OFF_PHI + tid] = ph;
    }

    // ---- pass 2: Pf = v @ Wf (outputs 64..127) -> S in-place (own column) ----
    {
        __half2 acc[32];
#pragma unroll
        for (int t = 0; t < 32; t++) acc[t] = hz;
#pragma unroll 4
        for (int kk = 0; kk < 64; kk++) {
            __half2 v2 = __float2half2_rn(sv[kk * SVS + tid]);
            const uint4* wr = reinterpret_cast<const uint4*>(sWh + kk * 128 + 64);
#pragma unroll
            for (int c = 0; c < 8; c++) {
                uint4 q = wr[c];
                acc[4 * c + 0] = __hfma2(v2, u2h2(q.x), acc[4 * c + 0]);
                acc[4 * c + 1] = __hfma2(v2, u2h2(q.y), acc[4 * c + 1]);
                acc[4 * c + 2] = __hfma2(v2, u2h2(q.z), acc[4 * c + 2]);
                acc[4 * c + 3] = __hfma2(v2, u2h2(q.w), acc[4 * c + 3]);
            }
        }
#pragma unroll
        for (int t = 0; t < 32; t++) {
            float2 f = __half22float2(acc[t]);
            sv[(2 * t) * SVS + tid] = silu_f(w * (f.x + dyn[OFF_BF + 2 * t]) + dyn[OFF_FB1 + 2 * t]);
            sv[(2 * t + 1) * SVS + tid] =
                silu_f(w * (f.y + dyn[OFF_BF + 2 * t + 1]) + dyn[OFF_FB1 + 2 * t + 1]);
        }
    }
    __syncthreads();

    // ---- epilogue: M[k][d], xacc, Dsum ----
    if (tid < 192) {
        int k = tid / 3, d = tid - 3 * k;
        const float* sp = sv + k * SVS;
        const float* dp = dyn + OFF_DIR + d * 256;
        float sacc = 0.f;
#pragma unroll 8
        for (int jj = 0; jj < 256; jj++) sacc += sp[jj] * dp[jj];
        atomicAdd(&g_M[i * 192 + k * 3 + d], sacc);
    } else if (tid < 195) {
        int d = tid - 192;
        const float* dp = dyn + OFF_DXR + d * 256;
        const float* pp = dyn + OFF_PHI;
        float sacc = 0.f;
#pragma unroll 8
        for (int jj = 0; jj < 256; jj++) sacc += dp[jj] * pp[jj];
        atomicAdd(&g_xacc[i * 3 + d], sacc);
    } else if (tid < 198) {
        int d = tid - 195;
        const float* dp = dyn + OFF_DIR + d * 256;
        float sacc = 0.f;
#pragma unroll 8
        for (int jj = 0; jj < 256; jj++) sacc += dp[jj];
        atomicAdd(&g_Dsum[i * 3 + d], sacc);
    }
}

// ---------------- K6: node-level MLPs + outputs -----------------------------------
__global__ void k_final(const float* __restrict__ h, const float* __restrict__ x,
                        const float* __restrict__ ew2, const float* __restrict__ eb2,
                        const float* __restrict__ nw1, const float* __restrict__ nb1,
                        const float* __restrict__ nw2, const float* __restrict__ nb2,
                        const float* __restrict__ pw1, const float* __restrict__ pb1,
                        const float* __restrict__ pw2, const float* __restrict__ pb2,
                        const float* __restrict__ fw2, const float* __restrict__ fb2,
                        float* __restrict__ out, int write_x) {
    __shared__ float sM[192], sq[32], p1[64], nin[192], n1[64], scv[64];
    int i = blockIdx.x, tid = threadIdx.x;
    scv[tid] = g_cv[i * 64 + tid];
    for (int t = tid; t < 192; t += 64) sM[t] = g_M[i * 192 + t];
    __syncthreads();
    if (tid < 32) {
        int c = tid;
        float ds0 = g_Dsum[i * 3 + 0], ds1 = g_Dsum[i * 3 + 1], ds2 = g_Dsum[i * 3 + 2];
        float fb = fb2[c];
        float a0 = fb * ds0, a1 = fb * ds1, a2 = fb * ds2;
#pragma unroll 8
        for (int k = 0; k < 64; k++) {
            float f = fw2[k * 32 + c];
            a0 += f * sM[k * 3 + 0];
            a1 += f * sM[k * 3 + 1];
            a2 += f * sM[k * 3 + 2];
        }
        a0 *= (1.f / 1024.f);
        a1 *= (1.f / 1024.f);
        a2 *= (1.f / 1024.f);
        sq[c] = a0 * a0 + a1 * a1 + a2 * a2;
    }
    __syncthreads();
    {
        float a = g_wsum[i] * eb2[tid];
#pragma unroll 8
        for (int m = 0; m < 64; m++) a += scv[m] * ew2[m * 64 + tid];
        nin[64 + tid] = a;
        float b = pb1[tid];
#pragma unroll
        for (int c = 0; c < 32; c++) b += sq[c] * pw1[c * 64 + tid];
        p1[tid] = silu_f(b);
        nin[tid] = h[i * 64 + tid];
    }
    __syncthreads();
    {
        float a = pb2[tid];
#pragma unroll 8
        for (int m = 0; m < 64; m++) a += p1[m] * pw2[m * 64 + tid];
        nin[128 + tid] = a;
    }
    __syncthreads();
    {
        float a = nb1[tid];
#pragma unroll 8
        for (int m = 0; m < 192; m++) a += nin[m] * nw1[m * 64 + tid];
        n1[tid] = silu_f(a);
    }
    __syncthreads();
    {
        float a = nb2[tid];
#pragma unroll 8
        for (int m = 0; m < 64; m++) a += n1[m] * nw2[m * 64 + tid];
        out[i * 64 + tid] = h[i * 64 + tid] + a;
    }
    if (write_x && tid < 3)
        out[NN * 64 + i * 3 + tid] = x[i * 3 + tid] + g_xacc[i * 3 + tid] * (1.f / 1024.f);
}

// ---------------- host -------------------------------------------------------------
extern "C" void kernel_launch(void* const* d_in, const int* in_sizes, int n_in,
                              void* d_out, int out_size) {
    const float* h = (const float*)d_in[0];
    const float* x = (const float*)d_in[1];
    const float* ew1 = (const float*)d_in[2];
    const float* eb1 = (const float*)d_in[3];
    const float* ew2 = (const float*)d_in[4];
    const float* eb2 = (const float*)d_in[5];
    const float* nw1 = (const float*)d_in[6];
    const float* nb1 = (const float*)d_in[7];
    const float* nw2 = (const float*)d_in[8];
    const float* nb2 = (const float*)d_in[9];
    const float* cw1 = (const float*)d_in[10];
    const float* cb1 = (const float*)d_in[11];
    const float* cw2 = (const float*)d_in[12];
    const float* aw = (const float*)d_in[13];
    const float* ab = (const float*)d_in[14];
    const float* fw1 = (const float*)d_in[15];
    const float* fb1 = (const float*)d_in[16];
    const float* fw2 = (const float*)d_in[17];
    const float* fb2 = (const float*)d_in[18];
    const float* pw1 = (const float*)d_in[19];
    const float* pb1 = (const float*)d_in[20];
    const float* pw2 = (const float*)d_in[21];
    const float* pb2 = (const float*)d_in[22];
    const float* lg = (const float*)d_in[23];
    float* out = (float*)d_out;

    const int K4_SMEM = K4_FLOATS * sizeof(float);  // 93968 B
    cudaFuncSetAttribute(k_pair, cudaFuncAttributeMaxDynamicSharedMemorySize, K4_SMEM);

    int write_x = (out_size >= NN * 64 + NN * 3) ? 1 : 0;

    k_zero<<<(NN * 192 + 255) / 256, 256>>>();
    k_fold<<<65, 64>>>(ew1, ew2, eb2, cw1, cb1, fw1, aw, ab);
    k_node_pre<<<NN, 64>>>(h, ew1, eb1);
    k_edge1<<<dim3(NN / 256, NN), 256>>>(x);
    k_attn<<<NN, 256>>>(x, lg);
    k_pair<<<dim3(NN / 256, NN), 256, K4_SMEM>>>(x, fb1, cw2);
    k_final<<<NN, 64>>>(h, x, ew2, eb2, nw1, nb1, nw2, nb2, pw1, pb1, pw2, pb2,
                        fw2, fb2, out, write_x);
}

// round 10
// speedup vs baseline: 1.9473x; 1.0486x over previous
#include <cuda_runtime.h>
#include <cuda_fp16.h>

#define NN 1024
#define EPSF 1e-5f
#define INFF 1e5f

typedef unsigned long long u64;
typedef unsigned int u32;

// ---------------- device scratch --------------------------------------------------
__device__ float g_A[NN * 64];                  // h@ew1[0:64] + eb1
__device__ float g_Bt[64 * NN];                 // h@ew1[64:128], k-major [k][j]
__device__ float g_slog[NN * NN];
__device__ float g_w[NN * NN];
__device__ float g_wsum[NN];
__device__ float g_cv[NN * 64];
__device__ float g_M[NN * 192];                 // M[i][k][d] = sum_j S * dir
__device__ float g_Dsum[NN * 3];
__device__ float g_xacc[NN * 3];
// folded weights
__device__ __half g_Wh[64 * 128];               // fp16, row k: [ew2@cw1 | ew2@fw1]
__device__ float g_bc[64];                      // eb2@cw1 + cb1
__device__ float g_bf1a[64];                    // eb2@fw1
__device__ float g_waw[64];                     // ew2@aw
__device__ float g_baw[1];                      // eb2.aw + ab
__device__ float g_Cw[64];                      // ew1 row 128

// ---------------- helpers ---------------------------------------------------------
__device__ __forceinline__ __half2 u2h2(u32 u) {
    __half2 h;
    *reinterpret_cast<u32*>(&h) = u;
    return h;
}
__device__ __forceinline__ float silu_f(float v) {          // exact-ish (2 MUFU)
    return __fdividef(v, 1.f + __expf(-v));
}
__device__ __forceinline__ float silu_fast(float v) {       // 1 MUFU via tanh
    float t;
    asm("tanh.approx.f32 %0, %1;" : "=f"(t) : "f"(0.5f * v));
    return v * fmaf(0.5f, t, 0.5f);
}

__device__ __forceinline__ float blk_red(float v, float* red, int tid, bool ismax) {
    red[tid] = v;
    __syncthreads();
#pragma unroll
    for (int s = 128; s >= 1; s >>= 1) {
        if (tid < s) red[tid] = ismax ? fmaxf(red[tid], red[tid + s]) : red[tid] + red[tid + s];
        __syncthreads();
    }
    float r = red[0];
    __syncthreads();
    return r;
}

// ---------------- K-zero ----------------------------------------------------------
__global__ void k_zero() {
    int idx = blockIdx.x * blockDim.x + threadIdx.x;
    if (idx < NN * 64) g_cv[idx] = 0.f;
    if (idx < NN * 192) g_M[idx] = 0.f;
    if (idx < NN * 3) { g_xacc[idx] = 0.f; g_Dsum[idx] = 0.f; }
}

// ---------------- k_fold ----------------------------------------------------------
__global__ void k_fold(const float* __restrict__ ew1, const float* __restrict__ ew2,
                       const float* __restrict__ eb2, const float* __restrict__ cw1,
                       const float* __restrict__ cb1, const float* __restrict__ fw1,
                       const float* __restrict__ aw, const float* __restrict__ ab) {
    int b = blockIdx.x, tid = threadIdx.x;  // 64 threads
    if (b < 64) {
        __shared__ float se[64];
        se[tid] = ew2[b * 64 + tid];
        __syncthreads();
        float ac = 0.f, af = 0.f;
#pragma unroll 8
        for (int k = 0; k < 64; k++) {
            float e = se[k];
            ac += e * cw1[k * 64 + tid];
            af += e * fw1[k * 64 + tid];
        }
        g_Wh[b * 128 + tid] = __float2half(ac);
        g_Wh[b * 128 + 64 + tid] = __float2half(af);
    } else {
        float sw = 0.f;
        for (int k = 0; k < 64; k++) sw += ew2[tid * 64 + k] * aw[k];
        g_waw[tid] = sw;
        float bc = cb1[tid], bf = 0.f;
        for (int k = 0; k < 64; k++) {
            bc += eb2[k] * cw1[k * 64 + tid];
            bf += eb2[k] * fw1[k * 64 + tid];
        }
        g_bc[tid] = bc;
        g_bf1a[tid] = bf;
        g_Cw[tid] = ew1[128 * 64 + tid];
        if (tid == 0) {
            float s = ab[0];
            for (int k = 0; k < 64; k++) s += eb2[k] * aw[k];
            g_baw[0] = s;
        }
    }
}

// ---------------- K0: per-node first-layer GEMVs ----------------------------------
__global__ void k_node_pre(const float* __restrict__ h, const float* __restrict__ ew1,
                           const float* __restrict__ eb1) {
    __shared__ float hr[64];
    int i = blockIdx.x, tid = threadIdx.x;
    hr[tid] = h[i * 64 + tid];
    __syncthreads();
    float a = eb1[tid], b = 0.f;
#pragma unroll 8
    for (int m = 0; m < 64; m++) {
        float hm = hr[m];
        a += hm * ew1[m * 64 + tid];
        b += hm * ew1[(64 + m) * 64 + tid];
    }
    g_A[i * 64 + tid] = a;
    g_Bt[tid * NN + i] = b;
}

// ---------------- K1: semantic logits ---------------------------------------------
__global__ void __launch_bounds__(256) k_edge1(const float* __restrict__ x) {
    __shared__ float sA[64], sC[64], sW[64], sXi[3], sBaw[1];
    int i = blockIdx.y, tid = threadIdx.x;
    int j = blockIdx.x * 256 + tid;
    if (tid < 64) {
        sA[tid] = g_A[i * 64 + tid];
        sC[tid] = g_Cw[tid];
        sW[tid] = g_waw[tid];
    }
    if (tid < 3) sXi[tid] = x[i * 3 + tid];
    if (tid == 0) sBaw[0] = g_baw[0];
    __syncthreads();

    float dx = sXi[0] - x[j * 3 + 0];
    float dy = sXi[1] - x[j * 3 + 1];
    float dz = sXi[2] - x[j * 3 + 2];
    float nrm = sqrtf(dx * dx + dy * dy + dz * dz + EPSF);

    float slog = sBaw[0];
#pragma unroll 8
    for (int k = 0; k < 64; k++) {
        float b = g_Bt[k * NN + j];
        slog += silu_f(sA[k] + b + nrm * sC[k]) * sW[k];
    }
    slog = (slog > 0.f) ? slog : 0.01f * slog;
    g_slog[i * NN + j] = slog;
}

// ---------------- K3: fused softmax combine ---------------------------------------
__global__ void k_attn(const float* __restrict__ x, const float* __restrict__ lg) {
    __shared__ float sls[NN], sle[NN];
    __shared__ float red[256];
    int i = blockIdx.x, tid = threadIdx.x;
    float gamma = __expf(lg[0]);
    float xi0 = x[i * 3 + 0], xi1 = x[i * 3 + 1], xi2 = x[i * 3 + 2];

    for (int j = tid; j < NN; j += 256) {
        float dx = xi0 - x[j * 3 + 0];
        float dy = xi1 - x[j * 3 + 1];
        float dz = xi2 - x[j * 3 + 2];
        float nrm = sqrtf(dx * dx + dy * dy + dz * dz + EPSF);
        float diag = (j == i) ? INFF : 0.f;
        sle[j] = -(nrm + diag) * gamma;
        sls[j] = g_slog[i * NN + j] - diag;
    }
    __syncthreads();

    float m = -3.4e38f;
    for (int j = tid; j < NN; j += 256) m = fmaxf(m, sls[j]);
    m = blk_red(m, red, tid, true);

    float ze = 0.f, zs = 0.f, tt = 0.f;
    for (int j = tid; j < NN; j += 256) {
        float le = sle[j], ls = sls[j] - m;
        ze += __expf(le);
        zs += __expf(ls);
        tt += __expf(le + ls);
    }
    ze = blk_red(ze, red, tid, false);
    zs = blk_red(zs, red, tid, false);
    tt = blk_red(tt, red, tid, false);

    float inv = 1.f / (tt + EPSF * ze * zs);
    for (int j = tid; j < NN; j += 256)
        g_w[i * NN + j] = __expf(sle[j] + sls[j] - m) * inv;
    if (tid == 0) g_wsum[i] = tt * inv;
}

// ---------------- K4: fused pair kernel (fp16 v/S in smem, 3 CTA/SM) --------------
// smem float offsets
#define OFF_WH   0          // 4096 floats = 8192 halfs (folded weights)
#define OFF_SVH  4096       // half[64 x 258]: v then S in-place (column-private)
#define SVH_STR  258
#define OFF_SWT  12352      // 256 (w)
#define OFF_BC   12608
#define OFF_BF   12672
#define OFF_FB1  12736
#define OFF_CW2  12800
#define OFF_A    12864
#define OFF_C    12928
#define OFF_XI   12992      // 4
#define OFF_CVP  12996      // 256
#define OFF_DIR  13252      // 3 x 256
#define OFF_SPHI 14020      // 256
#define K4_FLOATS 14276     // 57104 B

__global__ void __launch_bounds__(256, 3) k_pair(const float* __restrict__ x,
                                                 const float* __restrict__ fb1,
                                                 const float* __restrict__ cw2) {
    extern __shared__ __align__(16) float dyn[];
    __half* sWh = reinterpret_cast<__half*>(dyn + OFF_WH);
    __half* svh = reinterpret_cast<__half*>(dyn + OFF_SVH);
    float* swt = dyn + OFF_SWT;

    int i = blockIdx.y, tid = threadIdx.x;
    int j = blockIdx.x * 256 + tid;

    {
        const uint4* gW = reinterpret_cast<const uint4*>(g_Wh);
        uint4* sW = reinterpret_cast<uint4*>(sWh);
        for (int t = tid; t < 1024; t += 256) sW[t] = gW[t];
    }
    if (tid < 64) {
        dyn[OFF_BC + tid] = g_bc[tid];
        dyn[OFF_BF + tid] = g_bf1a[tid];
        dyn[OFF_FB1 + tid] = fb1[tid];
        dyn[OFF_CW2 + tid] = cw2[tid];
        dyn[OFF_A + tid] = g_A[i * 64 + tid];
        dyn[OFF_C + tid] = g_Cw[tid];
    }
    if (tid < 3) dyn[OFF_XI + tid] = x[i * 3 + tid];
    __syncthreads();

    // ---- phase A: geometry + v (exact silu; store fp16, column-private) ----
    float dxr0 = dyn[OFF_XI + 0] - x[j * 3 + 0];
    float dxr1 = dyn[OFF_XI + 1] - x[j * 3 + 1];
    float dxr2 = dyn[OFF_XI + 2] - x[j * 3 + 2];
    float nrm = sqrtf(dxr0 * dxr0 + dxr1 * dxr1 + dxr2 * dxr2 + EPSF);
    float inv1 = __fdividef(1.f, nrm + 1.f);
    float w = g_w[i * NN + j];
    swt[tid] = w;
    dyn[OFF_DIR + 0 * 256 + tid] = dxr0 * inv1;
    dyn[OFF_DIR + 1 * 256 + tid] = dxr1 * inv1;
    dyn[OFF_DIR + 2 * 256 + tid] = dxr2 * inv1;

#pragma unroll 8
    for (int k = 0; k < 64; k++) {
        float b = g_Bt[k * NN + j];
        svh[k * SVH_STR + tid] = __float2half(silu_f(dyn[OFF_A + k] + b + nrm * dyn[OFF_C + k]));
    }
    __syncthreads();

    // ---- cv = sum_j w*v ----
    {
        int k = tid & 63, qq = tid >> 6;
        const __half2* vp = reinterpret_cast<const __half2*>(svh + k * SVH_STR + qq * 64);
        const float* wp = swt + qq * 64;
        float sacc = 0.f;
#pragma unroll 8
        for (int m = 0; m < 32; m++) {
            __half2 p = vp[m];
            sacc += wp[2 * m] * __low2float(p) + wp[2 * m + 1] * __high2float(p);
        }
        dyn[OFF_CVP + k * 4 + qq] = sacc;
    }
    __syncthreads();
    if (tid < 64) {
        const float4 p = *reinterpret_cast<const float4*>(dyn + OFF_CVP + tid * 4);
        atomicAdd(&g_cv[i * 64 + tid], p.x + p.y + p.z + p.w);
    }

    // ---- pass 1: Pc = v @ Wc (outputs 0..63) -> phi ----
    const __half2 hz = __float2half2_rn(0.f);
    {
        __half2 acc[32];
#pragma unroll
        for (int t = 0; t < 32; t++) acc[t] = hz;
#pragma unroll 4
        for (int kk = 0; kk < 64; kk++) {
            __half2 v2 = __half2half2(svh[kk * SVH_STR + tid]);
            const uint4* wr = reinterpret_cast<const uint4*>(sWh + kk * 128);
#pragma unroll
            for (int c = 0; c < 8; c++) {
                uint4 q = wr[c];
                acc[4 * c + 0] = __hfma2(v2, u2h2(q.x), acc[4 * c + 0]);
                acc[4 * c + 1] = __hfma2(v2, u2h2(q.y), acc[4 * c + 1]);
                acc[4 * c + 2] = __hfma2(v2, u2h2(q.z), acc[4 * c + 2]);
                acc[4 * c + 3] = __hfma2(v2, u2h2(q.w), acc[4 * c + 3]);
            }
        }
        float ph = 0.f;
#pragma unroll
        for (int t = 0; t < 32; t++) {
            float2 f = __half22float2(acc[t]);
            ph += silu_fast(f.x + dyn[OFF_BC + 2 * t]) * dyn[OFF_CW2 + 2 * t];
            ph += silu_fast(f.y + dyn[OFF_BC + 2 * t + 1]) * dyn[OFF_CW2 + 2 * t + 1];
        }
        dyn[OFF_SPHI + tid] = ph * (nrm + 1.f);  // fold (nrm+1): xacc = sum dir * sphi
    }

    // ---- pass 2: Pf = v @ Wf (outputs 64..127) -> S in-place (own column) ----
    {
        __half2 acc[32];
#pragma unroll
        for (int t = 0; t < 32; t++) acc[t] = hz;
#pragma unroll 4
        for (int kk = 0; kk < 64; kk++) {
            __half2 v2 = __half2half2(svh[kk * SVH_STR + tid]);
            const uint4* wr = reinterpret_cast<const uint4*>(sWh + kk * 128 + 64);
#pragma unroll
            for (int c = 0; c < 8; c++) {
                uint4 q = wr[c];
                acc[4 * c + 0] = __hfma2(v2, u2h2(q.x), acc[4 * c + 0]);
                acc[4 * c + 1] = __hfma2(v2, u2h2(q.y), acc[4 * c + 1]);
                acc[4 * c + 2] = __hfma2(v2, u2h2(q.z), acc[4 * c + 2]);
                acc[4 * c + 3] = __hfma2(v2, u2h2(q.w), acc[4 * c + 3]);
            }
        }
#pragma unroll
        for (int t = 0; t < 32; t++) {
            float2 f = __half22float2(acc[t]);
            svh[(2 * t) * SVH_STR + tid] =
                __float2half(silu_fast(w * (f.x + dyn[OFF_BF + 2 * t]) + dyn[OFF_FB1 + 2 * t]));
            svh[(2 * t + 1) * SVH_STR + tid] =
                __float2half(silu_fast(w * (f.y + dyn[OFF_BF + 2 * t + 1]) + dyn[OFF_FB1 + 2 * t + 1]));
        }
    }
    __syncthreads();

    // ---- epilogue: M[k][d], xacc, Dsum ----
    if (tid < 192) {
        int k = tid / 3, d = tid - 3 * k;
        const __half2* sp = reinterpret_cast<const __half2*>(svh + k * SVH_STR);
        const float* dp = dyn + OFF_DIR + d * 256;
        float sacc = 0.f;
#pragma unroll 8
        for (int m = 0; m < 128; m++) {
            __half2 p = sp[m];
            sacc += __low2float(p) * dp[2 * m] + __high2float(p) * dp[2 * m + 1];
        }
        atomicAdd(&g_M[i * 192 + k * 3 + d], sacc);
    } else if (tid < 195) {
        int d = tid - 192;
        const float* dp = dyn + OFF_DIR + d * 256;
        const float* pp = dyn + OFF_SPHI;
        float sacc = 0.f;
#pragma unroll 8
        for (int jj = 0; jj < 256; jj++) sacc += dp[jj] * pp[jj];
        atomicAdd(&g_xacc[i * 3 + d], sacc);
    } else if (tid < 198) {
        int d = tid - 195;
        const float* dp = dyn + OFF_DIR + d * 256;
        float sacc = 0.f;
#pragma unroll 8
        for (int jj = 0; jj < 256; jj++) sacc += dp[jj];
        atomicAdd(&g_Dsum[i * 3 + d], sacc);
    }
}

// ---------------- K6: node-level MLPs + outputs -----------------------------------
__global__ void k_final(const float* __restrict__ h, const float* __restrict__ x,
                        const float* __restrict__ ew2, const float* __restrict__ eb2,
                        const float* __restrict__ nw1, const float* __restrict__ nb1,
                        const float* __restrict__ nw2, const float* __restrict__ nb2,
                        const float* __restrict__ pw1, const float* __restrict__ pb1,
                        const float* __restrict__ pw2, const float* __restrict__ pb2,
                        const float* __restrict__ fw2, const float* __restrict__ fb2,
                        float* __restrict__ out, int write_x) {
    __shared__ float sM[192], sq[32], p1[64], nin[192], n1[64], scv[64];
    int i = blockIdx.x, tid = threadIdx.x;
    scv[tid] = g_cv[i * 64 + tid];
    for (int t = tid; t < 192; t += 64) sM[t] = g_M[i * 192 + t];
    __syncthreads();
    if (tid < 32) {
        int c = tid;
        float ds0 = g_Dsum[i * 3 + 0], ds1 = g_Dsum[i * 3 + 1], ds2 = g_Dsum[i * 3 + 2];
        float fb = fb2[c];
        float a0 = fb * ds0, a1 = fb * ds1, a2 = fb * ds2;
#pragma unroll 8
        for (int k = 0; k < 64; k++) {
            float f = fw2[k * 32 + c];
            a0 += f * sM[k * 3 + 0];
            a1 += f * sM[k * 3 + 1];
            a2 += f * sM[k * 3 + 2];
        }
        a0 *= (1.f / 1024.f);
        a1 *= (1.f / 1024.f);
        a2 *= (1.f / 1024.f);
        sq[c] = a0 * a0 + a1 * a1 + a2 * a2;
    }
    __syncthreads();
    {
        float a = g_wsum[i] * eb2[tid];
#pragma unroll 8
        for (int m = 0; m < 64; m++) a += scv[m] * ew2[m * 64 + tid];
        nin[64 + tid] = a;
        float b = pb1[tid];
#pragma unroll
        for (int c = 0; c < 32; c++) b += sq[c] * pw1[c * 64 + tid];
        p1[tid] = silu_f(b);
        nin[tid] = h[i * 64 + tid];
    }
    __syncthreads();
    {
        float a = pb2[tid];
#pragma unroll 8
        for (int m = 0; m < 64; m++) a += p1[m] * pw2[m * 64 + tid];
        nin[128 + tid] = a;
    }
    __syncthreads();
    {
        float a = nb1[tid];
#pragma unroll 8
        for (int m = 0; m < 192; m++) a += nin[m] * nw1[m * 64 + tid];
        n1[tid] = silu_f(a);
    }
    __syncthreads();
    {
        float a = nb2[tid];
#pragma unroll 8
        for (int m = 0; m < 64; m++) a += n1[m] * nw2[m * 64 + tid];
        out[i * 64 + tid] = h[i * 64 + tid] + a;
    }
    if (write_x && tid < 3)
        out[NN * 64 + i * 3 + tid] = x[i * 3 + tid] + g_xacc[i * 3 + tid] * (1.f / 1024.f);
}

// ---------------- host -------------------------------------------------------------
extern "C" void kernel_launch(void* const* d_in, const int* in_sizes, int n_in,
                              void* d_out, int out_size) {
    const float* h = (const float*)d_in[0];
    const float* x = (const float*)d_in[1];
    const float* ew1 = (const float*)d_in[2];
    const float* eb1 = (const float*)d_in[3];
    const float* ew2 = (const float*)d_in[4];
    const float* eb2 = (const float*)d_in[5];
    const float* nw1 = (const float*)d_in[6];
    const float* nb1 = (const float*)d_in[7];
    const float* nw2 = (const float*)d_in[8];
    const float* nb2 = (const float*)d_in[9];
    const float* cw1 = (const float*)d_in[10];
    const float* cb1 = (const float*)d_in[11];
    const float* cw2 = (const float*)d_in[12];
    const float* aw = (const float*)d_in[13];
    const float* ab = (const float*)d_in[14];
    const float* fw1 = (const float*)d_in[15];
    const float* fb1 = (const float*)d_in[16];
    const float* fw2 = (const float*)d_in[17];
    const float* fb2 = (const float*)d_in[18];
    const float* pw1 = (const float*)d_in[19];
    const float* pb1 = (const float*)d_in[20];
    const float* pw2 = (const float*)d_in[21];
    const float* pb2 = (const float*)d_in[22];
    const float* lg = (const float*)d_in[23];
    float* out = (float*)d_out;

    const int K4_SMEM = K4_FLOATS * sizeof(float);  // 57104 B
    cudaFuncSetAttribute(k_pair, cudaFuncAttributeMaxDynamicSharedMemorySize, K4_SMEM);

    int write_x = (out_size >= NN * 64 + NN * 3) ? 1 : 0;

    k_zero<<<(NN * 192 + 255) / 256, 256>>>();
    k_fold<<<65, 64>>>(ew1, ew2, eb2, cw1, cb1, fw1, aw, ab);
    k_node_pre<<<NN, 64>>>(h, ew1, eb1);
    k_edge1<<<dim3(NN / 256, NN), 256>>>(x);
    k_attn<<<NN, 256>>>(x, lg);
    k_pair<<<dim3(NN / 256, NN), 256, K4_SMEM>>>(x, fb1, cw2);
    k_final<<<NN, 64>>>(h, x, ew2, eb2, nw1, nb1, nw2, nb2, pw1, pb1, pw2, pb2,
                        fw2, fb2, out, write_x);
}

// round 11
// speedup vs baseline: 1.9511x; 1.0020x over previous
#include <cuda_runtime.h>
#include <cuda_fp16.h>

#define NN 1024
#define EPSF 1e-5f
#define INFF 1e5f

typedef unsigned long long u64;
typedef unsigned int u32;

// ---------------- device scratch --------------------------------------------------
__device__ float g_A[NN * 64];                  // h@ew1[0:64] + eb1
__device__ float g_Bt[64 * NN];                 // h@ew1[64:128], k-major [k][j]
__device__ float g_slog[NN * NN];
__device__ float g_w[NN * NN];
__device__ float g_wsum[NN];
__device__ float g_cv[NN * 64];
__device__ float g_M[NN * 192];                 // M[i][k][d] = sum_j S * dir
__device__ float g_Dsum[NN * 3];
__device__ float g_xacc[NN * 3];
// folded weights
__device__ __half g_Wh[64 * 128];               // fp16, row k: [ew2@cw1 | ew2@fw1]
__device__ float g_bc[64];                      // eb2@cw1 + cb1
__device__ float g_bf1a[64];                    // eb2@fw1
__device__ float g_waw[64];                     // ew2@aw
__device__ float g_baw[1];                      // eb2.aw + ab
__device__ float g_Cw[64];                      // ew1 row 128

// ---------------- helpers ---------------------------------------------------------
__device__ __forceinline__ __half2 u2h2(u32 u) {
    __half2 h;
    *reinterpret_cast<u32*>(&h) = u;
    return h;
}
__device__ __forceinline__ float silu_f(float v) {          // exact-ish (2 MUFU)
    return __fdividef(v, 1.f + __expf(-v));
}
__device__ __forceinline__ float silu_fast(float v) {       // 1 MUFU via tanh
    float t;
    asm("tanh.approx.f32 %0, %1;" : "=f"(t) : "f"(0.5f * v));
    return v * fmaf(0.5f, t, 0.5f);
}

// ---------------- K-zero ----------------------------------------------------------
__global__ void k_zero() {
    int idx = blockIdx.x * blockDim.x + threadIdx.x;
    if (idx < NN * 64) g_cv[idx] = 0.f;
    if (idx < NN * 192) g_M[idx] = 0.f;
    if (idx < NN * 3) { g_xacc[idx] = 0.f; g_Dsum[idx] = 0.f; }
}

// ---------------- k_fold ----------------------------------------------------------
__global__ void k_fold(const float* __restrict__ ew1, const float* __restrict__ ew2,
                       const float* __restrict__ eb2, const float* __restrict__ cw1,
                       const float* __restrict__ cb1, const float* __restrict__ fw1,
                       const float* __restrict__ aw, const float* __restrict__ ab) {
    int b = blockIdx.x, tid = threadIdx.x;  // 64 threads
    if (b < 64) {
        __shared__ float se[64];
        se[tid] = ew2[b * 64 + tid];
        __syncthreads();
        float ac = 0.f, af = 0.f;
#pragma unroll 8
        for (int k = 0; k < 64; k++) {
            float e = se[k];
            ac += e * cw1[k * 64 + tid];
            af += e * fw1[k * 64 + tid];
        }
        g_Wh[b * 128 + tid] = __float2half(ac);
        g_Wh[b * 128 + 64 + tid] = __float2half(af);
    } else {
        float sw = 0.f;
        for (int k = 0; k < 64; k++) sw += ew2[tid * 64 + k] * aw[k];
        g_waw[tid] = sw;
        float bc = cb1[tid], bf = 0.f;
        for (int k = 0; k < 64; k++) {
            bc += eb2[k] * cw1[k * 64 + tid];
            bf += eb2[k] * fw1[k * 64 + tid];
        }
        g_bc[tid] = bc;
        g_bf1a[tid] = bf;
        g_Cw[tid] = ew1[128 * 64 + tid];
        if (tid == 0) {
            float s = ab[0];
            for (int k = 0; k < 64; k++) s += eb2[k] * aw[k];
            g_baw[0] = s;
        }
    }
}

// ---------------- K0: per-node first-layer GEMVs ----------------------------------
__global__ void k_node_pre(const float* __restrict__ h, const float* __restrict__ ew1,
                           const float* __restrict__ eb1) {
    __shared__ float hr[64];
    int i = blockIdx.x, tid = threadIdx.x;
    hr[tid] = h[i * 64 + tid];
    __syncthreads();
    float a = eb1[tid], b = 0.f;
#pragma unroll 8
    for (int m = 0; m < 64; m++) {
        float hm = hr[m];
        a += hm * ew1[m * 64 + tid];
        b += hm * ew1[(64 + m) * 64 + tid];
    }
    g_A[i * 64 + tid] = a;
    g_Bt[tid * NN + i] = b;
}

// ---------------- K1: semantic logits ---------------------------------------------
__global__ void __launch_bounds__(256) k_edge1(const float* __restrict__ x) {
    __shared__ float sA[64], sC[64], sW[64], sXi[3], sBaw[1];
    int i = blockIdx.y, tid = threadIdx.x;
    int j = blockIdx.x * 256 + tid;
    if (tid < 64) {
        sA[tid] = g_A[i * 64 + tid];
        sC[tid] = g_Cw[tid];
        sW[tid] = g_waw[tid];
    }
    if (tid < 3) sXi[tid] = x[i * 3 + tid];
    if (tid == 0) sBaw[0] = g_baw[0];
    __syncthreads();

    float dx = sXi[0] - x[j * 3 + 0];
    float dy = sXi[1] - x[j * 3 + 1];
    float dz = sXi[2] - x[j * 3 + 2];
    float nrm = sqrtf(dx * dx + dy * dy + dz * dz + EPSF);

    float slog = sBaw[0];
#pragma unroll 8
    for (int k = 0; k < 64; k++) {
        float b = g_Bt[k * NN + j];
        slog += silu_fast(sA[k] + b + nrm * sC[k]) * sW[k];
    }
    slog = (slog > 0.f) ? slog : 0.01f * slog;
    g_slog[i * NN + j] = slog;
}

// ---------------- K3: fused softmax combine (shuffle reductions) -------------------
__global__ void __launch_bounds__(256) k_attn(const float* __restrict__ x,
                                              const float* __restrict__ lg) {
    __shared__ float sls[NN], sle[NN];
    __shared__ float red[24];
    int i = blockIdx.x, tid = threadIdx.x;
    int lane = tid & 31, wid = tid >> 5;
    float gamma = __expf(lg[0]);
    float xi0 = x[i * 3 + 0], xi1 = x[i * 3 + 1], xi2 = x[i * 3 + 2];

    for (int j = tid; j < NN; j += 256) {
        float dx = xi0 - x[j * 3 + 0];
        float dy = xi1 - x[j * 3 + 1];
        float dz = xi2 - x[j * 3 + 2];
        float nrm = sqrtf(dx * dx + dy * dy + dz * dz + EPSF);
        float diag = (j == i) ? INFF : 0.f;
        sle[j] = -(nrm + diag) * gamma;
        sls[j] = g_slog[i * NN + j] - diag;
    }
    __syncthreads();

    // max over sls
    float m = -3.4e38f;
    for (int j = tid; j < NN; j += 256) m = fmaxf(m, sls[j]);
#pragma unroll
    for (int o = 16; o; o >>= 1) m = fmaxf(m, __shfl_xor_sync(~0u, m, o));
    if (lane == 0) red[wid] = m;
    __syncthreads();
    m = red[0];
#pragma unroll
    for (int t = 1; t < 8; t++) m = fmaxf(m, red[t]);

    // sums
    float ze = 0.f, zs = 0.f, tt = 0.f;
    for (int j = tid; j < NN; j += 256) {
        float le = sle[j], ls = sls[j] - m;
        ze += __expf(le);
        zs += __expf(ls);
        tt += __expf(le + ls);
    }
#pragma unroll
    for (int o = 16; o; o >>= 1) {
        ze += __shfl_xor_sync(~0u, ze, o);
        zs += __shfl_xor_sync(~0u, zs, o);
        tt += __shfl_xor_sync(~0u, tt, o);
    }
    __syncthreads();
    if (lane == 0) { red[wid] = ze; red[8 + wid] = zs; red[16 + wid] = tt; }
    __syncthreads();
    ze = zs = tt = 0.f;
#pragma unroll
    for (int t = 0; t < 8; t++) { ze += red[t]; zs += red[8 + t]; tt += red[16 + t]; }

    float inv = 1.f / (tt + EPSF * ze * zs);
    for (int j = tid; j < NN; j += 256)
        g_w[i * NN + j] = __expf(sle[j] + sls[j] - m) * inv;
    if (tid == 0) g_wsum[i] = tt * inv;
}

// ---------------- K4: fused pair kernel (fp16 v/S in smem, 4 CTA/SM) --------------
// smem float offsets
#define OFF_WH   0          // 4096 floats = 8192 halfs (folded weights)
#define OFF_SVH  4096       // half[64 x 258]: v then S in-place (column-private)
#define SVH_STR  258
#define OFF_SWT  12352      // 256 (w)
#define OFF_BC   12608
#define OFF_BF   12672
#define OFF_FB1  12736
#define OFF_CW2  12800
#define OFF_A    12864
#define OFF_C    12928
#define OFF_XI   12992      // 4
#define OFF_CVP  12996      // 256
#define OFF_DIR  13252      // 3 x 256
#define OFF_SPHI 14020      // 256
#define K4_FLOATS 14276     // 57104 B

__global__ void __launch_bounds__(256, 4) k_pair(const float* __restrict__ x,
                                                 const float* __restrict__ fb1,
                                                 const float* __restrict__ cw2) {
    extern __shared__ __align__(16) float dyn[];
    __half* sWh = reinterpret_cast<__half*>(dyn + OFF_WH);
    __half* svh = reinterpret_cast<__half*>(dyn + OFF_SVH);
    float* swt = dyn + OFF_SWT;

    int i = blockIdx.y, tid = threadIdx.x;
    int j = blockIdx.x * 256 + tid;

    {
        const uint4* gW = reinterpret_cast<const uint4*>(g_Wh);
        uint4* sW = reinterpret_cast<uint4*>(sWh);
        for (int t = tid; t < 1024; t += 256) sW[t] = gW[t];
    }
    if (tid < 64) {
        dyn[OFF_BC + tid] = g_bc[tid];
        dyn[OFF_BF + tid] = g_bf1a[tid];
        dyn[OFF_FB1 + tid] = fb1[tid];
        dyn[OFF_CW2 + tid] = cw2[tid];
        dyn[OFF_A + tid] = g_A[i * 64 + tid];
        dyn[OFF_C + tid] = g_Cw[tid];
    }
    if (tid < 3) dyn[OFF_XI + tid] = x[i * 3 + tid];
    __syncthreads();

    // ---- phase A: geometry + v (fast silu; store fp16, column-private) ----
    float dxr0 = dyn[OFF_XI + 0] - x[j * 3 + 0];
    float dxr1 = dyn[OFF_XI + 1] - x[j * 3 + 1];
    float dxr2 = dyn[OFF_XI + 2] - x[j * 3 + 2];
    float nrm = sqrtf(dxr0 * dxr0 + dxr1 * dxr1 + dxr2 * dxr2 + EPSF);
    float inv1 = __fdividef(1.f, nrm + 1.f);
    float w = g_w[i * NN + j];
    swt[tid] = w;
    dyn[OFF_DIR + 0 * 256 + tid] = dxr0 * inv1;
    dyn[OFF_DIR + 1 * 256 + tid] = dxr1 * inv1;
    dyn[OFF_DIR + 2 * 256 + tid] = dxr2 * inv1;

#pragma unroll 8
    for (int k = 0; k < 64; k++) {
        float b = g_Bt[k * NN + j];
        svh[k * SVH_STR + tid] = __float2half(silu_fast(dyn[OFF_A + k] + b + nrm * dyn[OFF_C + k]));
    }
    __syncthreads();

    // ---- cv = sum_j w*v ----
    {
        int k = tid & 63, qq = tid >> 6;
        const __half2* vp = reinterpret_cast<const __half2*>(svh + k * SVH_STR + qq * 64);
        const float* wp = swt + qq * 64;
        float sacc = 0.f;
#pragma unroll 8
        for (int m = 0; m < 32; m++) {
            __half2 p = vp[m];
            sacc += wp[2 * m] * __low2float(p) + wp[2 * m + 1] * __high2float(p);
        }
        dyn[OFF_CVP + k * 4 + qq] = sacc;
    }
    __syncthreads();
    if (tid < 64) {
        const float4 p = *reinterpret_cast<const float4*>(dyn + OFF_CVP + tid * 4);
        atomicAdd(&g_cv[i * 64 + tid], p.x + p.y + p.z + p.w);
    }

    // ---- pass 1: Pc = v @ Wc (outputs 0..63) -> phi ----
    const __half2 hz = __float2half2_rn(0.f);
    {
        __half2 acc[32];
#pragma unroll
        for (int t = 0; t < 32; t++) acc[t] = hz;
#pragma unroll 4
        for (int kk = 0; kk < 64; kk++) {
            __half2 v2 = __half2half2(svh[kk * SVH_STR + tid]);
            const uint4* wr = reinterpret_cast<const uint4*>(sWh + kk * 128);
#pragma unroll
            for (int c = 0; c < 8; c++) {
                uint4 q = wr[c];
                acc[4 * c + 0] = __hfma2(v2, u2h2(q.x), acc[4 * c + 0]);
                acc[4 * c + 1] = __hfma2(v2, u2h2(q.y), acc[4 * c + 1]);
                acc[4 * c + 2] = __hfma2(v2, u2h2(q.z), acc[4 * c + 2]);
                acc[4 * c + 3] = __hfma2(v2, u2h2(q.w), acc[4 * c + 3]);
            }
        }
        float ph = 0.f;
#pragma unroll
        for (int t = 0; t < 32; t++) {
            float2 f = __half22float2(acc[t]);
            ph += silu_fast(f.x + dyn[OFF_BC + 2 * t]) * dyn[OFF_CW2 + 2 * t];
            ph += silu_fast(f.y + dyn[OFF_BC + 2 * t + 1]) * dyn[OFF_CW2 + 2 * t + 1];
        }
        dyn[OFF_SPHI + tid] = ph * (nrm + 1.f);  // fold (nrm+1): xacc = sum dir * sphi
    }

    // ---- pass 2: Pf = v @ Wf (outputs 64..127) -> S in-place (own column) ----
    {
        __half2 acc[32];
#pragma unroll
        for (int t = 0; t < 32; t++) acc[t] = hz;
#pragma unroll 4
        for (int kk = 0; kk < 64; kk++) {
            __half2 v2 = __half2half2(svh[kk * SVH_STR + tid]);
            const uint4* wr = reinterpret_cast<const uint4*>(sWh + kk * 128 + 64);
#pragma unroll
            for (int c = 0; c < 8; c++) {
                uint4 q = wr[c];
                acc[4 * c + 0] = __hfma2(v2, u2h2(q.x), acc[4 * c + 0]);
                acc[4 * c + 1] = __hfma2(v2, u2h2(q.y), acc[4 * c + 1]);
                acc[4 * c + 2] = __hfma2(v2, u2h2(q.z), acc[4 * c + 2]);
                acc[4 * c + 3] = __hfma2(v2, u2h2(q.w), acc[4 * c + 3]);
            }
        }
#pragma unroll
        for (int t = 0; t < 32; t++) {
            float2 f = __half22float2(acc[t]);
            svh[(2 * t) * SVH_STR + tid] =
                __float2half(silu_fast(w * (f.x + dyn[OFF_BF + 2 * t]) + dyn[OFF_FB1 + 2 * t]));
            svh[(2 * t + 1) * SVH_STR + tid] =
                __float2half(silu_fast(w * (f.y + dyn[OFF_BF + 2 * t + 1]) + dyn[OFF_FB1 + 2 * t + 1]));
        }
    }
    __syncthreads();

    // ---- epilogue: M[k][d], xacc, Dsum ----
    if (tid < 192) {
        int k = tid / 3, d = tid - 3 * k;
        const __half2* sp = reinterpret_cast<const __half2*>(svh + k * SVH_STR);
        const float* dp = dyn + OFF_DIR + d * 256;
        float sacc = 0.f;
#pragma unroll 8
        for (int m = 0; m < 128; m++) {
            __half2 p = sp[m];
            sacc += __low2float(p) * dp[2 * m] + __high2float(p) * dp[2 * m + 1];
        }
        atomicAdd(&g_M[i * 192 + k * 3 + d], sacc);
    } else if (tid < 195) {
        int d = tid - 192;
        const float* dp = dyn + OFF_DIR + d * 256;
        const float* pp = dyn + OFF_SPHI;
        float sacc = 0.f;
#pragma unroll 8
        for (int jj = 0; jj < 256; jj++) sacc += dp[jj] * pp[jj];
        atomicAdd(&g_xacc[i * 3 + d], sacc);
    } else if (tid < 198) {
        int d = tid - 195;
        const float* dp = dyn + OFF_DIR + d * 256;
        float sacc = 0.f;
#pragma unroll 8
        for (int jj = 0; jj < 256; jj++) sacc += dp[jj];
        atomicAdd(&g_Dsum[i * 3 + d], sacc);
    }
}

// ---------------- K6: node-level MLPs + outputs -----------------------------------
__global__ void k_final(const float* __restrict__ h, const float* __restrict__ x,
                        const float* __restrict__ ew2, const float* __restrict__ eb2,
                        const float* __restrict__ nw1, const float* __restrict__ nb1,
                        const float* __restrict__ nw2, const float* __restrict__ nb2,
                        const float* __restrict__ pw1, const float* __restrict__ pb1,
                        const float* __restrict__ pw2, const float* __restrict__ pb2,
                        const float* __restrict__ fw2, const float* __restrict__ fb2,
                        float* __restrict__ out, int write_x) {
    __shared__ float sM[192], sq[32], p1[64], nin[192], n1[64], scv[64];
    int i = blockIdx.x, tid = threadIdx.x;
    scv[tid] = g_cv[i * 64 + tid];
    for (int t = tid; t < 192; t += 64) sM[t] = g_M[i * 192 + t];
    __syncthreads();
    if (tid < 32) {
        int c = tid;
        float ds0 = g_Dsum[i * 3 + 0], ds1 = g_Dsum[i * 3 + 1], ds2 = g_Dsum[i * 3 + 2];
        float fb = fb2[c];
        float a0 = fb * ds0, a1 = fb * ds1, a2 = fb * ds2;
#pragma unroll 8
        for (int k = 0; k < 64; k++) {
            float f = fw2[k * 32 + c];
            a0 += f * sM[k * 3 + 0];
            a1 += f * sM[k * 3 + 1];
            a2 += f * sM[k * 3 + 2];
        }
        a0 *= (1.f / 1024.f);
        a1 *= (1.f / 1024.f);
        a2 *= (1.f / 1024.f);
        sq[c] = a0 * a0 + a1 * a1 + a2 * a2;
    }
    __syncthreads();
    {
        float a = g_wsum[i] * eb2[tid];
#pragma unroll 8
        for (int m = 0; m < 64; m++) a += scv[m] * ew2[m * 64 + tid];
        nin[64 + tid] = a;
        float b = pb1[tid];
#pragma unroll
        for (int c = 0; c < 32; c++) b += sq[c] * pw1[c * 64 + tid];
        p1[tid] = silu_f(b);
        nin[tid] = h[i * 64 + tid];
    }
    __syncthreads();
    {
        float a = pb2[tid];
#pragma unroll 8
        for (int m = 0; m < 64; m++) a += p1[m] * pw2[m * 64 + tid];
        nin[128 + tid] = a;
    }
    __syncthreads();
    {
        float a = nb1[tid];
#pragma unroll 8
        for (int m = 0; m < 192; m++) a += nin[m] * nw1[m * 64 + tid];
        n1[tid] = silu_f(a);
    }
    __syncthreads();
    {
        float a = nb2[tid];
#pragma unroll 8
        for (int m = 0; m < 64; m++) a += n1[m] * nw2[m * 64 + tid];
        out[i * 64 + tid] = h[i * 64 + tid] + a;
    }
    if (write_x && tid < 3)
        out[NN * 64 + i * 3 + tid] = x[i * 3 + tid] + g_xacc[i * 3 + tid] * (1.f / 1024.f);
}

// ---------------- host -------------------------------------------------------------
extern "C" void kernel_launch(void* const* d_in, const int* in_sizes, int n_in,
                              void* d_out, int out_size) {
    const float* h = (const float*)d_in[0];
    const float* x = (const float*)d_in[1];
    const float* ew1 = (const float*)d_in[2];
    const float* eb1 = (const float*)d_in[3];
    const float* ew2 = (const float*)d_in[4];
    const float* eb2 = (const float*)d_in[5];
    const float* nw1 = (const float*)d_in[6];
    const float* nb1 = (const float*)d_in[7];
    const float* nw2 = (const float*)d_in[8];
    const float* nb2 = (const float*)d_in[9];
    const float* cw1 = (const float*)d_in[10];
    const float* cb1 = (const float*)d_in[11];
    const float* cw2 = (const float*)d_in[12];
    const float* aw = (const float*)d_in[13];
    const float* ab = (const float*)d_in[14];
    const float* fw1 = (const float*)d_in[15];
    const float* fb1 = (const float*)d_in[16];
    const float* fw2 = (const float*)d_in[17];
    const float* fb2 = (const float*)d_in[18];
    const float* pw1 = (const float*)d_in[19];
    const float* pb1 = (const float*)d_in[20];
    const float* pw2 = (const float*)d_in[21];
    const float* pb2 = (const float*)d_in[22];
    const float* lg = (const float*)d_in[23];
    float* out = (float*)d_out;

    const int K4_SMEM = K4_FLOATS * sizeof(float);  // 57104 B
    cudaFuncSetAttribute(k_pair, cudaFuncAttributeMaxDynamicSharedMemorySize, K4_SMEM);
    cudaFuncSetAttribute(k_pair, cudaFuncAttributePreferredSharedMemoryCarveout, 100);

    int write_x = (out_size >= NN * 64 + NN * 3) ? 1 : 0;

    k_zero<<<(NN * 192 + 255) / 256, 256>>>();
    k_fold<<<65, 64>>>(ew1, ew2, eb2, cw1, cb1, fw1, aw, ab);
    k_node_pre<<<NN, 64>>>(h, ew1, eb1);
    k_edge1<<<dim3(NN / 256, NN), 256>>>(x);
    k_attn<<<NN, 256>>>(x, lg);
    k_pair<<<dim3(NN / 256, NN), 256, K4_SMEM>>>(x, fb1, cw2);
    k_final<<<NN, 64>>>(h, x, ew2, eb2, nw1, nb1, nw2, nb2, pw1, pb1, pw2, pb2,
                        fw2, fb2, out, write_x);
}

// round 13
// speedup vs baseline: 2.3101x; 1.1840x over previous
#include <cuda_runtime.h>
#include <cuda_fp16.h>

#define NN 1024
#define EPSF 1e-5f
#define INFF 1e5f

typedef unsigned long long u64;
typedef unsigned int u32;

// ---------------- device scratch --------------------------------------------------
__device__ float g_A[NN * 64];                  // h@ew1[0:64] + eb1
__device__ float g_Bt[64 * NN];                 // h@ew1[64:128], k-major [k][j]
__device__ float g_slog[NN * NN];
__device__ float g_w[NN * NN];
__device__ float g_wsum[NN];
__device__ float g_cv[NN * 64];
__device__ float g_M[NN * 192];                 // M[i][k][d] = sum_j S * dir
__device__ float g_Dsum[NN * 3];
__device__ float g_xacc[NN * 3];
// folded weights
__device__ __half g_Wh[64 * 128];               // fp16, row k: [ew2@cw1 | ew2@fw1]
__device__ float g_bc[64];                      // eb2@cw1 + cb1
__device__ float g_bf1a[64];                    // eb2@fw1
__device__ float g_waw[64];                     // ew2@aw
__device__ float g_baw[1];                      // eb2.aw + ab
__device__ float g_Cw[64];                      // ew1 row 128

// ---------------- helpers ---------------------------------------------------------
__device__ __forceinline__ __half2 u2h2(u32 u) {
    __half2 h;
    *reinterpret_cast<u32*>(&h) = u;
    return h;
}
__device__ __forceinline__ float silu_f(float v) {          // exact-ish (2 MUFU)
    return __fdividef(v, 1.f + __expf(-v));
}
__device__ __forceinline__ float silu_fast(float v) {       // 1 MUFU via tanh
    float t;
    asm("tanh.approx.f32 %0, %1;" : "=f"(t) : "f"(0.5f * v));
    return v * fmaf(0.5f, t, 0.5f);
}
__device__ __forceinline__ __half2 silu_h2(__half2 z) {     // 2 silus, 1 MUFU
    const __half2 h05 = __float2half2_rn(0.5f);
    __half2 zh = __hmul2(z, h05);
    u32 zi = *reinterpret_cast<u32*>(&zh), ti;
    asm("tanh.approx.f16x2 %0, %1;" : "=r"(ti) : "r"(zi));
    __half2 t = *reinterpret_cast<__half2*>(&ti);
    return __hmul2(z, __hfma2(t, h05, h05));
}

// ---------------- K-zero ----------------------------------------------------------
__global__ void k_zero() {
    int idx = blockIdx.x * blockDim.x + threadIdx.x;
    if (idx < NN * 64) g_cv[idx] = 0.f;
    if (idx < NN * 192) g_M[idx] = 0.f;
    if (idx < NN * 3) { g_xacc[idx] = 0.f; g_Dsum[idx] = 0.f; }
}

// ---------------- k_fold ----------------------------------------------------------
__global__ void k_fold(const float* __restrict__ ew1, const float* __restrict__ ew2,
                       const float* __restrict__ eb2, const float* __restrict__ cw1,
                       const float* __restrict__ cb1, const float* __restrict__ fw1,
                       const float* __restrict__ aw, const float* __restrict__ ab) {
    int b = blockIdx.x, tid = threadIdx.x;  // 64 threads
    if (b < 64) {
        __shared__ float se[64];
        se[tid] = ew2[b * 64 + tid];
        __syncthreads();
        float ac = 0.f, af = 0.f;
#pragma unroll 8
        for (int k = 0; k < 64; k++) {
            float e = se[k];
            ac += e * cw1[k * 64 + tid];
            af += e * fw1[k * 64 + tid];
        }
        g_Wh[b * 128 + tid] = __float2half(ac);
        g_Wh[b * 128 + 64 + tid] = __float2half(af);
    } else {
        float sw = 0.f;
        for (int k = 0; k < 64; k++) sw += ew2[tid * 64 + k] * aw[k];
        g_waw[tid] = sw;
        float bc = cb1[tid], bf = 0.f;
        for (int k = 0; k < 64; k++) {
            bc += eb2[k] * cw1[k * 64 + tid];
            bf += eb2[k] * fw1[k * 64 + tid];
        }
        g_bc[tid] = bc;
        g_bf1a[tid] = bf;
        g_Cw[tid] = ew1[128 * 64 + tid];
        if (tid == 0) {
            float s = ab[0];
            for (int k = 0; k < 64; k++) s += eb2[k] * aw[k];
            g_baw[0] = s;
        }
    }
}

// ---------------- K0: per-node first-layer GEMVs ----------------------------------
__global__ void k_node_pre(const float* __restrict__ h, const float* __restrict__ ew1,
                           const float* __restrict__ eb1) {
    __shared__ float hr[64];
    int i = blockIdx.x, tid = threadIdx.x;
    hr[tid] = h[i * 64 + tid];
    __syncthreads();
    float a = eb1[tid], b = 0.f;
#pragma unroll 8
    for (int m = 0; m < 64; m++) {
        float hm = hr[m];
        a += hm * ew1[m * 64 + tid];
        b += hm * ew1[(64 + m) * 64 + tid];
    }
    g_A[i * 64 + tid] = a;
    g_Bt[tid * NN + i] = b;
}

// ---------------- K1: semantic logits ---------------------------------------------
__global__ void __launch_bounds__(256) k_edge1(const float* __restrict__ x) {
    __shared__ float sA[64], sC[64], sW[64], sXi[3], sBaw[1];
    int i = blockIdx.y, tid = threadIdx.x;
    int j = blockIdx.x * 256 + tid;
    if (tid < 64) {
        sA[tid] = g_A[i * 64 + tid];
        sC[tid] = g_Cw[tid];
        sW[tid] = g_waw[tid];
    }
    if (tid < 3) sXi[tid] = x[i * 3 + tid];
    if (tid == 0) sBaw[0] = g_baw[0];
    __syncthreads();

    float dx = sXi[0] - x[j * 3 + 0];
    float dy = sXi[1] - x[j * 3 + 1];
    float dz = sXi[2] - x[j * 3 + 2];
    float nrm = sqrtf(dx * dx + dy * dy + dz * dz + EPSF);

    float slog = sBaw[0];
#pragma unroll 8
    for (int k = 0; k < 64; k++) {
        float b = g_Bt[k * NN + j];
        slog += silu_fast(sA[k] + b + nrm * sC[k]) * sW[k];
    }
    slog = (slog > 0.f) ? slog : 0.01f * slog;
    g_slog[i * NN + j] = slog;
}

// ---------------- K3: fused softmax combine (shuffle reductions) -------------------
__global__ void __launch_bounds__(256) k_attn(const float* __restrict__ x,
                                              const float* __restrict__ lg) {
    __shared__ float sls[NN], sle[NN];
    __shared__ float red[24];
    int i = blockIdx.x, tid = threadIdx.x;
    int lane = tid & 31, wid = tid >> 5;
    float gamma = __expf(lg[0]);
    float xi0 = x[i * 3 + 0], xi1 = x[i * 3 + 1], xi2 = x[i * 3 + 2];

    for (int j = tid; j < NN; j += 256) {
        float dx = xi0 - x[j * 3 + 0];
        float dy = xi1 - x[j * 3 + 1];
        float dz = xi2 - x[j * 3 + 2];
        float nrm = sqrtf(dx * dx + dy * dy + dz * dz + EPSF);
        float diag = (j == i) ? INFF : 0.f;
        sle[j] = -(nrm + diag) * gamma;
        sls[j] = g_slog[i * NN + j] - diag;
    }
    __syncthreads();

    float m = -3.4e38f;
    for (int j = tid; j < NN; j += 256) m = fmaxf(m, sls[j]);
#pragma unroll
    for (int o = 16; o; o >>= 1) m = fmaxf(m, __shfl_xor_sync(~0u, m, o));
    if (lane == 0) red[wid] = m;
    __syncthreads();
    m = red[0];
#pragma unroll
    for (int t = 1; t < 8; t++) m = fmaxf(m, red[t]);

    float ze = 0.f, zs = 0.f, tt = 0.f;
    for (int j = tid; j < NN; j += 256) {
        float le = sle[j], ls = sls[j] - m;
        ze += __expf(le);
        zs += __expf(ls);
        tt += __expf(le + ls);
    }
#pragma unroll
    for (int o = 16; o; o >>= 1) {
        ze += __shfl_xor_sync(~0u, ze, o);
        zs += __shfl_xor_sync(~0u, zs, o);
        tt += __shfl_xor_sync(~0u, tt, o);
    }
    __syncthreads();
    if (lane == 0) { red[wid] = ze; red[8 + wid] = zs; red[16 + wid] = tt; }
    __syncthreads();
    ze = zs = tt = 0.f;
#pragma unroll
    for (int t = 0; t < 8; t++) { ze += red[t]; zs += red[8 + t]; tt += red[16 + t]; }

    float inv = 1.f / (tt + EPSF * ze * zs);
    for (int j = tid; j < NN; j += 256)
        g_w[i * NN + j] = __expf(sle[j] + sls[j] - m) * inv;
    if (tid == 0) g_wsum[i] = tt * inv;
}

// ---------------- K4: fused pair kernel (half2 nonlinear diet, FIXED offsets) -----
// smem float offsets — each half2[32] region now correctly sized at 32 floats
#define OFF_WH   0          // 4096 floats = 8192 halfs (folded weights)
#define OFF_SVH  4096       // half[64 x 258]: v then S in-place (column-private)
#define SVH_STR  258
#define OFF_SWT  12352      // 256 (w)
#define OFF_BC2  12608      // half2[32] = 32 floats
#define OFF_BF2  12640      // half2[32] = 32 floats
#define OFF_FB1H 12672      // half2[32] = 32 floats
#define OFF_CW2H 12704      // half2[32] = 32 floats
#define OFF_A    12736      // 64
#define OFF_C    12800      // 64
#define OFF_XI   12864      // 4
#define OFF_CVP  12868      // 256
#define OFF_DIR  13124      // 3 x 256 fp32 (xacc/Dsum threads)
#define OFF_SDH  13892      // half[3 x 260] dirs = 390 floats (M epilogue)
#define OFF_SPHI 14284      // 256
#define K4_FLOATS 14540     // 58160 B

__global__ void __launch_bounds__(256, 3) k_pair(const float* __restrict__ x,
                                                 const float* __restrict__ fb1,
                                                 const float* __restrict__ cw2) {
    extern __shared__ __align__(16) float dyn[];
    __half* sWh = reinterpret_cast<__half*>(dyn + OFF_WH);
    __half* svh = reinterpret_cast<__half*>(dyn + OFF_SVH);
    __half* sdh = reinterpret_cast<__half*>(dyn + OFF_SDH);
    float* swt = dyn + OFF_SWT;

    int i = blockIdx.y, tid = threadIdx.x;
    int j = blockIdx.x * 256 + tid;

    {
        const uint4* gW = reinterpret_cast<const uint4*>(g_Wh);
        uint4* sW = reinterpret_cast<uint4*>(sWh);
        for (int t = tid; t < 1024; t += 256) sW[t] = gW[t];
    }
    if (tid < 32) {
        reinterpret_cast<__half2*>(dyn + OFF_BC2)[tid] =
            __floats2half2_rn(g_bc[2 * tid], g_bc[2 * tid + 1]);
        reinterpret_cast<__half2*>(dyn + OFF_BF2)[tid] =
            __floats2half2_rn(g_bf1a[2 * tid], g_bf1a[2 * tid + 1]);
        reinterpret_cast<__half2*>(dyn + OFF_FB1H)[tid] =
            __floats2half2_rn(fb1[2 * tid], fb1[2 * tid + 1]);
        reinterpret_cast<__half2*>(dyn + OFF_CW2H)[tid] =
            __floats2half2_rn(cw2[2 * tid], cw2[2 * tid + 1]);
    }
    if (tid < 64) {
        dyn[OFF_A + tid] = g_A[i * 64 + tid];
        dyn[OFF_C + tid] = g_Cw[tid];
    }
    if (tid < 3) dyn[OFF_XI + tid] = x[i * 3 + tid];
    __syncthreads();

    // ---- phase A: geometry + v (fast silu fp32; store fp16, column-private) ----
    float dxr0 = dyn[OFF_XI + 0] - x[j * 3 + 0];
    float dxr1 = dyn[OFF_XI + 1] - x[j * 3 + 1];
    float dxr2 = dyn[OFF_XI + 2] - x[j * 3 + 2];
    float nrm = sqrtf(dxr0 * dxr0 + dxr1 * dxr1 + dxr2 * dxr2 + EPSF);
    float inv1 = __fdividef(1.f, nrm + 1.f);
    float w = g_w[i * NN + j];
    swt[tid] = w;
    float d0 = dxr0 * inv1, d1 = dxr1 * inv1, d2 = dxr2 * inv1;
    dyn[OFF_DIR + 0 * 256 + tid] = d0;
    dyn[OFF_DIR + 1 * 256 + tid] = d1;
    dyn[OFF_DIR + 2 * 256 + tid] = d2;
    sdh[0 * 260 + tid] = __float2half(d0);
    sdh[1 * 260 + tid] = __float2half(d1);
    sdh[2 * 260 + tid] = __float2half(d2);

#pragma unroll 8
    for (int k = 0; k < 64; k++) {
        float b = g_Bt[k * NN + j];
        svh[k * SVH_STR + tid] = __float2half(silu_fast(dyn[OFF_A + k] + b + nrm * dyn[OFF_C + k]));
    }
    __syncthreads();

    // ---- cv = sum_j w*v (fp32, sensitive path) ----
    {
        int k = tid & 63, qq = tid >> 6;
        const __half2* vp = reinterpret_cast<const __half2*>(svh + k * SVH_STR + qq * 64);
        const float* wp = swt + qq * 64;
        float sacc = 0.f;
#pragma unroll 8
        for (int m = 0; m < 32; m++) {
            __half2 p = vp[m];
            sacc += wp[2 * m] * __low2float(p) + wp[2 * m + 1] * __high2float(p);
        }
        dyn[OFF_CVP + k * 4 + qq] = sacc;
    }
    __syncthreads();
    if (tid < 64) {
        const float4 p = *reinterpret_cast<const float4*>(dyn + OFF_CVP + tid * 4);
        atomicAdd(&g_cv[i * 64 + tid], p.x + p.y + p.z + p.w);
    }

    const __half2 hz = __float2half2_rn(0.f);

    // ---- pass 1: Pc = v @ Wc (outputs 0..63) -> phi (half2 epilogue) ----
    {
        __half2 acc[32];
#pragma unroll
        for (int t = 0; t < 32; t++) acc[t] = hz;
#pragma unroll 4
        for (int kk = 0; kk < 64; kk++) {
            __half2 v2 = __half2half2(svh[kk * SVH_STR + tid]);
            const uint4* wr = reinterpret_cast<const uint4*>(sWh + kk * 128);
#pragma unroll
            for (int c = 0; c < 8; c++) {
                uint4 q = wr[c];
                acc[4 * c + 0] = __hfma2(v2, u2h2(q.x), acc[4 * c + 0]);
                acc[4 * c + 1] = __hfma2(v2, u2h2(q.y), acc[4 * c + 1]);
                acc[4 * c + 2] = __hfma2(v2, u2h2(q.z), acc[4 * c + 2]);
                acc[4 * c + 3] = __hfma2(v2, u2h2(q.w), acc[4 * c + 3]);
            }
        }
        const __half2* bc2 = reinterpret_cast<const __half2*>(dyn + OFF_BC2);
        const __half2* cw2h = reinterpret_cast<const __half2*>(dyn + OFF_CW2H);
        __half2 ph2 = hz;
#pragma unroll
        for (int t = 0; t < 32; t++)
            ph2 = __hfma2(silu_h2(__hadd2(acc[t], bc2[t])), cw2h[t], ph2);
        float phi = __low2float(ph2) + __high2float(ph2);
        dyn[OFF_SPHI + tid] = phi * (nrm + 1.f);  // xacc = sum dir * sphi
    }

    // ---- pass 2: Pf = v @ Wf (outputs 64..127) -> S in-place (half2 epilogue) ----
    {
        __half2 acc[32];
#pragma unroll
        for (int t = 0; t < 32; t++) acc[t] = hz;
#pragma unroll 4
        for (int kk = 0; kk < 64; kk++) {
            __half2 v2 = __half2half2(svh[kk * SVH_STR + tid]);
            const uint4* wr = reinterpret_cast<const uint4*>(sWh + kk * 128 + 64);
#pragma unroll
            for (int c = 0; c < 8; c++) {
                uint4 q = wr[c];
                acc[4 * c + 0] = __hfma2(v2, u2h2(q.x), acc[4 * c + 0]);
                acc[4 * c + 1] = __hfma2(v2, u2h2(q.y), acc[4 * c + 1]);
                acc[4 * c + 2] = __hfma2(v2, u2h2(q.z), acc[4 * c + 2]);
                acc[4 * c + 3] = __hfma2(v2, u2h2(q.w), acc[4 * c + 3]);
            }
        }
        const __half2* bf2 = reinterpret_cast<const __half2*>(dyn + OFF_BF2);
        const __half2* fb1h = reinterpret_cast<const __half2*>(dyn + OFF_FB1H);
        __half2 w2 = __float2half2_rn(w);
#pragma unroll
        for (int t = 0; t < 32; t++) {
            __half2 s2 = silu_h2(__hfma2(w2, __hadd2(acc[t], bf2[t]), fb1h[t]));
            svh[(2 * t) * SVH_STR + tid] = __low2half(s2);
            svh[(2 * t + 1) * SVH_STR + tid] = __high2half(s2);
        }
    }
    __syncthreads();

    // ---- epilogue: M[k][d] (half2 chunked), xacc, Dsum ----
    if (tid < 192) {
        int k = tid / 3, d = tid - 3 * k;
        const __half2* sp = reinterpret_cast<const __half2*>(svh + k * SVH_STR);
        const __half2* dph = reinterpret_cast<const __half2*>(sdh + d * 260);
        float accf = 0.f;
#pragma unroll
        for (int ch = 0; ch < 4; ch++) {
            __half2 a2 = hz;
#pragma unroll 8
            for (int m = ch * 32; m < ch * 32 + 32; m++) a2 = __hfma2(sp[m], dph[m], a2);
            accf += __low2float(a2) + __high2float(a2);
        }
        atomicAdd(&g_M[i * 192 + k * 3 + d], accf);
    } else if (tid < 195) {
        int d = tid - 192;
        const float* dp = dyn + OFF_DIR + d * 256;
        const float* pp = dyn + OFF_SPHI;
        float sacc = 0.f;
#pragma unroll 8
        for (int jj = 0; jj < 256; jj++) sacc += dp[jj] * pp[jj];
        atomicAdd(&g_xacc[i * 3 + d], sacc);
    } else if (tid < 198) {
        int d = tid - 195;
        const float* dp = dyn + OFF_DIR + d * 256;
        float sacc = 0.f;
#pragma unroll 8
        for (int jj = 0; jj < 256; jj++) sacc += dp[jj];
        atomicAdd(&g_Dsum[i * 3 + d], sacc);
    }
}

// ---------------- K6: node-level MLPs + outputs -----------------------------------
__global__ void k_final(const float* __restrict__ h, const float* __restrict__ x,
                        const float* __restrict__ ew2, const float* __restrict__ eb2,
                        const float* __restrict__ nw1, const float* __restrict__ nb1,
                        const float* __restrict__ nw2, const float* __restrict__ nb2,
                        const float* __restrict__ pw1, const float* __restrict__ pb1,
                        const float* __restrict__ pw2, const float* __restrict__ pb2,
                        const float* __restrict__ fw2, const float* __restrict__ fb2,
                        float* __restrict__ out, int write_x) {
    __shared__ float sM[192], sq[32], p1[64], nin[192], n1[64], scv[64];
    int i = blockIdx.x, tid = threadIdx.x;
    scv[tid] = g_cv[i * 64 + tid];
    for (int t = tid; t < 192; t += 64) sM[t] = g_M[i * 192 + t];
    __syncthreads();
    if (tid < 32) {
        int c = tid;
        float ds0 = g_Dsum[i * 3 + 0], ds1 = g_Dsum[i * 3 + 1], ds2 = g_Dsum[i * 3 + 2];
        float fb = fb2[c];
        float a0 = fb * ds0, a1 = fb * ds1, a2 = fb * ds2;
#pragma unroll 8
        for (int k = 0; k < 64; k++) {
            float f = fw2[k * 32 + c];
            a0 += f * sM[k * 3 + 0];
            a1 += f * sM[k * 3 + 1];
            a2 += f * sM[k * 3 + 2];
        }
        a0 *= (1.f / 1024.f);
        a1 *= (1.f / 1024.f);
        a2 *= (1.f / 1024.f);
        sq[c] = a0 * a0 + a1 * a1 + a2 * a2;
    }
    __syncthreads();
    {
        float a = g_wsum[i] * eb2[tid];
#pragma unroll 8
        for (int m = 0; m < 64; m++) a += scv[m] * ew2[m * 64 + tid];
        nin[64 + tid] = a;
        float b = pb1[tid];
#pragma unroll
        for (int c = 0; c < 32; c++) b += sq[c] * pw1[c * 64 + tid];
        p1[tid] = silu_f(b);
        nin[tid] = h[i * 64 + tid];
    }
    __syncthreads();
    {
        float a = pb2[tid];
#pragma unroll 8
        for (int m = 0; m < 64; m++) a += p1[m] * pw2[m * 64 + tid];
        nin[128 + tid] = a;
    }
    __syncthreads();
    {
        float a = nb1[tid];
#pragma unroll 8
        for (int m = 0; m < 192; m++) a += nin[m] * nw1[m * 64 + tid];
        n1[tid] = silu_f(a);
    }
    __syncthreads();
    {
        float a = nb2[tid];
#pragma unroll 8
        for (int m = 0; m < 64; m++) a += n1[m] * nw2[m * 64 + tid];
        out[i * 64 + tid] = h[i * 64 + tid] + a;
    }
    if (write_x && tid < 3)
        out[NN * 64 + i * 3 + tid] = x[i * 3 + tid] + g_xacc[i * 3 + tid] * (1.f / 1024.f);
}

// ---------------- host -------------------------------------------------------------
extern "C" void kernel_launch(void* const* d_in, const int* in_sizes, int n_in,
                              void* d_out, int out_size) {
    const float* h = (const float*)d_in[0];
    const float* x = (const float*)d_in[1];
    const float* ew1 = (const float*)d_in[2];
    const float* eb1 = (const float*)d_in[3];
    const float* ew2 = (const float*)d_in[4];
    const float* eb2 = (const float*)d_in[5];
    const float* nw1 = (const float*)d_in[6];
    const float* nb1 = (const float*)d_in[7];
    const float* nw2 = (const float*)d_in[8];
    const float* nb2 = (const float*)d_in[9];
    const float* cw1 = (const float*)d_in[10];
    const float* cb1 = (const float*)d_in[11];
    const float* cw2 = (const float*)d_in[12];
    const float* aw = (const float*)d_in[13];
    const float* ab = (const float*)d_in[14];
    const float* fw1 = (const float*)d_in[15];
    const float* fb1 = (const float*)d_in[16];
    const float* fw2 = (const float*)d_in[17];
    const float* fb2 = (const float*)d_in[18];
    const float* pw1 = (const float*)d_in[19];
    const float* pb1 = (const float*)d_in[20];
    const float* pw2 = (const float*)d_in[21];
    const float* pb2 = (const float*)d_in[22];
    const float* lg = (const float*)d_in[23];
    float* out = (float*)d_out;

    const int K4_SMEM = K4_FLOATS * sizeof(float);  // 58160 B
    cudaFuncSetAttribute(k_pair, cudaFuncAttributeMaxDynamicSharedMemorySize, K4_SMEM);

    int write_x = (out_size >= NN * 64 + NN * 3) ? 1 : 0;

    k_zero<<<(NN * 192 + 255) / 256, 256>>>();
    k_fold<<<65, 64>>>(ew1, ew2, eb2, cw1, cb1, fw1, aw, ab);
    k_node_pre<<<NN, 64>>>(h, ew1, eb1);
    k_edge1<<<dim3(NN / 256, NN), 256>>>(x);
    k_attn<<<NN, 256>>>(x, lg);
    k_pair<<<dim3(NN / 256, NN), 256, K4_SMEM>>>(x, fb1, cw2);
    k_final<<<NN, 64>>>(h, x, ew2, eb2, nw1, nb1, nw2, nb2, pw1, pb1, pw2, pb2,
                        fw2, fb2, out, write_x);
}

// round 15
// speedup vs baseline: 2.4296x; 1.0517x over previous
#include <cuda_runtime.h>
#include <cuda_fp16.h>

#define NN 1024
#define EPSF 1e-5f
#define INFF 1e5f

typedef unsigned long long u64;
typedef unsigned int u32;

// ---------------- device scratch --------------------------------------------------
__device__ float g_A[NN * 64];                  // h@ew1[0:64] + eb1
__device__ float g_Bt[64 * NN];                 // h@ew1[64:128], k-major [k][j]
__device__ float g_w[NN * NN];
__device__ float g_wsum[NN];
__device__ __align__(16) float g_cv[NN * 64];
__device__ __align__(16) float g_M[NN * 192];   // M[i][k][d] = sum_j S * dir
__device__ __align__(16) float g_Dsum[NN * 4];  // padded to /4
__device__ __align__(16) float g_xacc[NN * 4];  // padded to /4
// folded weights
__device__ __half g_Wh[64 * 128];               // fp16, row k: [ew2@cw1 | ew2@fw1]
__device__ float g_bc[64];                      // eb2@cw1 + cb1
__device__ float g_bf1a[64];                    // eb2@fw1
__device__ float g_waw[64];                     // ew2@aw
__device__ float g_baw[1];                      // eb2.aw + ab
__device__ float g_Cw[64];                      // ew1 row 128

// ---------------- helpers ---------------------------------------------------------
__device__ __forceinline__ __half2 u2h2(u32 u) {
    __half2 h;
    *reinterpret_cast<u32*>(&h) = u;
    return h;
}
__device__ __forceinline__ float silu_f(float v) {          // exact-ish (2 MUFU)
    return __fdividef(v, 1.f + __expf(-v));
}
__device__ __forceinline__ float silu_fast(float v) {       // 1 MUFU via tanh
    float t;
    asm("tanh.approx.f32 %0, %1;" : "=f"(t) : "f"(0.5f * v));
    return v * fmaf(0.5f, t, 0.5f);
}
__device__ __forceinline__ __half2 silu_h2(__half2 z) {     // 2 silus, 1 MUFU
    const __half2 h05 = __float2half2_rn(0.5f);
    __half2 zh = __hmul2(z, h05);
    u32 zi = *reinterpret_cast<u32*>(&zh), ti;
    asm("tanh.approx.f16x2 %0, %1;" : "=r"(ti) : "r"(zi));
    __half2 t = *reinterpret_cast<__half2*>(&ti);
    return __hmul2(z, __hfma2(t, h05, h05));
}

// ---------------- k_prep: fold + node_pre + zero, block-range dispatch -------------
// grid layout (64-thread blocks):
//   [0,64)        : fold row b
//   64            : fold extras (waw, bc, bf1a, Cw, baw)
//   [65,1089)     : node_pre for i = b-65
//   [1089,1857)   : zero g_M     (768 blocks x 64 f4 = 49152 f4 = NN*192 floats)
//   [1857,2113)   : zero g_cv    (256 blocks x 64 f4 = 16384 f4 = NN*64 floats)
//   [2113,2129)   : zero g_xacc  (16 blocks x 64 f4 = 1024 f4 = NN*4 floats)
//   [2129,2145)   : zero g_Dsum  (16 blocks x 64 f4 = 1024 f4 = NN*4 floats)
#define PREP_GRID 2145
__global__ void k_prep(const float* __restrict__ h, const float* __restrict__ ew1,
                       const float* __restrict__ eb1, const float* __restrict__ ew2,
                       const float* __restrict__ eb2, const float* __restrict__ cw1,
                       const float* __restrict__ cb1, const float* __restrict__ fw1,
                       const float* __restrict__ aw, const float* __restrict__ ab) {
    int b = blockIdx.x, tid = threadIdx.x;
    if (b < 64) {
        __shared__ float se[64];
        se[tid] = ew2[b * 64 + tid];
        __syncthreads();
        float ac = 0.f, af = 0.f;
#pragma unroll 8
        for (int k = 0; k < 64; k++) {
            float e = se[k];
            ac += e * cw1[k * 64 + tid];
            af += e * fw1[k * 64 + tid];
        }
        g_Wh[b * 128 + tid] = __float2half(ac);
        g_Wh[b * 128 + 64 + tid] = __float2half(af);
    } else if (b == 64) {
        float sw = 0.f;
        for (int k = 0; k < 64; k++) sw += ew2[tid * 64 + k] * aw[k];
        g_waw[tid] = sw;
        float bc = cb1[tid], bf = 0.f;
        for (int k = 0; k < 64; k++) {
            bc += eb2[k] * cw1[k * 64 + tid];
            bf += eb2[k] * fw1[k * 64 + tid];
        }
        g_bc[tid] = bc;
        g_bf1a[tid] = bf;
        g_Cw[tid] = ew1[128 * 64 + tid];
        if (tid == 0) {
            float s = ab[0];
            for (int k = 0; k < 64; k++) s += eb2[k] * aw[k];
            g_baw[0] = s;
        }
    } else if (b < 1089) {
        int i = b - 65;
        __shared__ float hr[64];
        hr[tid] = h[i * 64 + tid];
        __syncthreads();
        float a = eb1[tid], bb = 0.f;
#pragma unroll 8
        for (int m = 0; m < 64; m++) {
            float hm = hr[m];
            a += hm * ew1[m * 64 + tid];
            bb += hm * ew1[(64 + m) * 64 + tid];
        }
        g_A[i * 64 + tid] = a;
        g_Bt[tid * NN + i] = bb;
    } else {
        const float4 z4 = make_float4(0.f, 0.f, 0.f, 0.f);
        if (b < 1857) {
            reinterpret_cast<float4*>(g_M)[(b - 1089) * 64 + tid] = z4;
        } else if (b < 2113) {
            reinterpret_cast<float4*>(g_cv)[(b - 1857) * 64 + tid] = z4;
        } else if (b < 2129) {
            reinterpret_cast<float4*>(g_xacc)[(b - 2113) * 64 + tid] = z4;
        } else {
            reinterpret_cast<float4*>(g_Dsum)[(b - 2129) * 64 + tid] = z4;
        }
    }
}

// ---------------- k_edge_attn: fused slog + softmax combine -----------------------
__global__ void __launch_bounds__(256) k_edge_attn(const float* __restrict__ x,
                                                   const float* __restrict__ lg) {
    __shared__ float sls[NN], sle[NN];
    __shared__ float sA[64], sC[64], sW[64];
    __shared__ float red[24];
    int i = blockIdx.x, tid = threadIdx.x;
    int lane = tid & 31, wid = tid >> 5;
    if (tid < 64) {
        sA[tid] = g_A[i * 64 + tid];
        sC[tid] = g_Cw[tid];
        sW[tid] = g_waw[tid];
    }
    __syncthreads();
    float gamma = __expf(lg[0]);
    float baw = g_baw[0];
    float xi0 = x[i * 3 + 0], xi1 = x[i * 3 + 1], xi2 = x[i * 3 + 2];

    for (int j = tid; j < NN; j += 256) {
        float dx = xi0 - x[j * 3 + 0];
        float dy = xi1 - x[j * 3 + 1];
        float dz = xi2 - x[j * 3 + 2];
        float nrm = sqrtf(dx * dx + dy * dy + dz * dz + EPSF);
        float slog = baw;
#pragma unroll 8
        for (int k = 0; k < 64; k++)
            slog += silu_fast(sA[k] + g_Bt[k * NN + j] + nrm * sC[k]) * sW[k];
        slog = (slog > 0.f) ? slog : 0.01f * slog;
        float diag = (j == i) ? INFF : 0.f;
        sle[j] = -(nrm + diag) * gamma;
        sls[j] = slog - diag;
    }
    __syncthreads();

    float m = -3.4e38f;
    for (int j = tid; j < NN; j += 256) m = fmaxf(m, sls[j]);
#pragma unroll
    for (int o = 16; o; o >>= 1) m = fmaxf(m, __shfl_xor_sync(~0u, m, o));
    if (lane == 0) red[wid] = m;
    __syncthreads();
    m = red[0];
#pragma unroll
    for (int t = 1; t < 8; t++) m = fmaxf(m, red[t]);

    float ze = 0.f, zs = 0.f, tt = 0.f;
    for (int j = tid; j < NN; j += 256) {
        float le = sle[j], ls = sls[j] - m;
        ze += __expf(le);
        zs += __expf(ls);
        tt += __expf(le + ls);
    }
#pragma unroll
    for (int o = 16; o; o >>= 1) {
        ze += __shfl_xor_sync(~0u, ze, o);
        zs += __shfl_xor_sync(~0u, zs, o);
        tt += __shfl_xor_sync(~0u, tt, o);
    }
    __syncthreads();
    if (lane == 0) { red[wid] = ze; red[8 + wid] = zs; red[16 + wid] = tt; }
    __syncthreads();
    ze = zs = tt = 0.f;
#pragma unroll
    for (int t = 0; t < 8; t++) { ze += red[t]; zs += red[8 + t]; tt += red[16 + t]; }

    float inv = 1.f / (tt + EPSF * ze * zs);
    for (int j = tid; j < NN; j += 256)
        g_w[i * NN + j] = __expf(sle[j] + sls[j] - m) * inv;
    if (tid == 0) g_wsum[i] = tt * inv;
}

// ---------------- K4: fused pair kernel (bias-folded acc init) --------------------
// smem float offsets
#define OFF_WH   0          // 4096 floats = 8192 halfs (folded weights)
#define OFF_SVH  4096       // half[64 x 258]: v then S in-place (column-private)
#define SVH_STR  258
#define OFF_SWT  12352      // 256 (w)
#define OFF_BC2  12608      // half2[32] = 32 floats
#define OFF_BF2  12640      // half2[32] = 32 floats
#define OFF_FB1H 12672      // half2[32] = 32 floats
#define OFF_CW2H 12704      // half2[32] = 32 floats
#define OFF_A    12736      // 64
#define OFF_C    12800      // 64
#define OFF_XI   12864      // 4
#define OFF_CVP  12868      // 256
#define OFF_DIR  13124      // 3 x 256 fp32 (xacc/Dsum threads)
#define OFF_SDH  13892      // half[3 x 260] dirs = 390 floats (M epilogue)
#define OFF_SPHI 14284      // 256
#define K4_FLOATS 14540     // 58160 B

__global__ void __launch_bounds__(256, 3) k_pair(const float* __restrict__ x,
                                                 const float* __restrict__ fb1,
                                                 const float* __restrict__ cw2) {
    extern __shared__ __align__(16) float dyn[];
    __half* sWh = reinterpret_cast<__half*>(dyn + OFF_WH);
    __half* svh = reinterpret_cast<__half*>(dyn + OFF_SVH);
    __half* sdh = reinterpret_cast<__half*>(dyn + OFF_SDH);
    float* swt = dyn + OFF_SWT;

    int i = blockIdx.y, tid = threadIdx.x;
    int j = blockIdx.x * 256 + tid;

    {
        const uint4* gW = reinterpret_cast<const uint4*>(g_Wh);
        uint4* sW = reinterpret_cast<uint4*>(sWh);
        for (int t = tid; t < 1024; t += 256) sW[t] = gW[t];
    }
    if (tid < 32) {
        reinterpret_cast<__half2*>(dyn + OFF_BC2)[tid] =
            __floats2half2_rn(g_bc[2 * tid], g_bc[2 * tid + 1]);
        reinterpret_cast<__half2*>(dyn + OFF_BF2)[tid] =
            __floats2half2_rn(g_bf1a[2 * tid], g_bf1a[2 * tid + 1]);
        reinterpret_cast<__half2*>(dyn + OFF_FB1H)[tid] =
            __floats2half2_rn(fb1[2 * tid], fb1[2 * tid + 1]);
        reinterpret_cast<__half2*>(dyn + OFF_CW2H)[tid] =
            __floats2half2_rn(cw2[2 * tid], cw2[2 * tid + 1]);
    }
    if (tid < 64) {
        dyn[OFF_A + tid] = g_A[i * 64 + tid];
        dyn[OFF_C + tid] = g_Cw[tid];
    }
    if (tid < 3) dyn[OFF_XI + tid] = x[i * 3 + tid];
    __syncthreads();

    // ---- phase A: geometry + v (fast silu fp32; store fp16, column-private) ----
    float dxr0 = dyn[OFF_XI + 0] - x[j * 3 + 0];
    float dxr1 = dyn[OFF_XI + 1] - x[j * 3 + 1];
    float dxr2 = dyn[OFF_XI + 2] - x[j * 3 + 2];
    float nrm = sqrtf(dxr0 * dxr0 + dxr1 * dxr1 + dxr2 * dxr2 + EPSF);
    float inv1 = __fdividef(1.f, nrm + 1.f);
    float w = g_w[i * NN + j];
    swt[tid] = w;
    float d0 = dxr0 * inv1, d1 = dxr1 * inv1, d2 = dxr2 * inv1;
    dyn[OFF_DIR + 0 * 256 + tid] = d0;
    dyn[OFF_DIR + 1 * 256 + tid] = d1;
    dyn[OFF_DIR + 2 * 256 + tid] = d2;
    sdh[0 * 260 + tid] = __float2half(d0);
    sdh[1 * 260 + tid] = __float2half(d1);
    sdh[2 * 260 + tid] = __float2half(d2);

#pragma unroll 8
    for (int k = 0; k < 64; k++) {
        float b = g_Bt[k * NN + j];
        svh[k * SVH_STR + tid] = __float2half(silu_fast(dyn[OFF_A + k] + b + nrm * dyn[OFF_C + k]));
    }
    __syncthreads();

    // ---- cv = sum_j w*v (fp32, sensitive path) ----
    {
        int k = tid & 63, qq = tid >> 6;
        const __half2* vp = reinterpret_cast<const __half2*>(svh + k * SVH_STR + qq * 64);
        const float* wp = swt + qq * 64;
        float sacc = 0.f;
#pragma unroll 8
        for (int m = 0; m < 32; m++) {
            __half2 p = vp[m];
            sacc += wp[2 * m] * __low2float(p) + wp[2 * m + 1] * __high2float(p);
        }
        dyn[OFF_CVP + k * 4 + qq] = sacc;
    }
    __syncthreads();
    if (tid < 64) {
        const float4 p = *reinterpret_cast<const float4*>(dyn + OFF_CVP + tid * 4);
        atomicAdd(&g_cv[i * 64 + tid], p.x + p.y + p.z + p.w);
    }

    const __half2 hz = __float2half2_rn(0.f);

    // ---- pass 1: Pc = v @ Wc + bc (acc init = bc2) -> phi ----
    {
        const __half2* bc2 = reinterpret_cast<const __half2*>(dyn + OFF_BC2);
        __half2 acc[32];
#pragma unroll
        for (int t = 0; t < 32; t++) acc[t] = bc2[t];
#pragma unroll 4
        for (int kk = 0; kk < 64; kk++) {
            __half2 v2 = __half2half2(svh[kk * SVH_STR + tid]);
            const uint4* wr = reinterpret_cast<const uint4*>(sWh + kk * 128);
#pragma unroll
            for (int c = 0; c < 8; c++) {
                uint4 q = wr[c];
                acc[4 * c + 0] = __hfma2(v2, u2h2(q.x), acc[4 * c + 0]);
                acc[4 * c + 1] = __hfma2(v2, u2h2(q.y), acc[4 * c + 1]);
                acc[4 * c + 2] = __hfma2(v2, u2h2(q.z), acc[4 * c + 2]);
                acc[4 * c + 3] = __hfma2(v2, u2h2(q.w), acc[4 * c + 3]);
            }
        }
        const __half2* cw2h = reinterpret_cast<const __half2*>(dyn + OFF_CW2H);
        __half2 ph2 = hz;
#pragma unroll
        for (int t = 0; t < 32; t++)
            ph2 = __hfma2(silu_h2(acc[t]), cw2h[t], ph2);
        float phi = __low2float(ph2) + __high2float(ph2);
        dyn[OFF_SPHI + tid] = phi * (nrm + 1.f);  // xacc = sum dir * sphi
    }

    // ---- pass 2: Pf = v @ Wf + bf (acc init = bf2) -> S in-place ----
    {
        const __half2* bf2 = reinterpret_cast<const __half2*>(dyn + OFF_BF2);
        __half2 acc[32];
#pragma unroll
        for (int t = 0; t < 32; t++) acc[t] = bf2[t];
#pragma unroll 4
        for (int kk = 0; kk < 64; kk++) {
            __half2 v2 = __half2half2(svh[kk * SVH_STR + tid]);
            const uint4* wr = reinterpret_cast<const uint4*>(sWh + kk * 128 + 64);
#pragma unroll
            for (int c = 0; c < 8; c++) {
                uint4 q = wr[c];
                acc[4 * c + 0] = __hfma2(v2, u2h2(q.x), acc[4 * c + 0]);
                acc[4 * c + 1] = __hfma2(v2, u2h2(q.y), acc[4 * c + 1]);
                acc[4 * c + 2] = __hfma2(v2, u2h2(q.z), acc[4 * c + 2]);
                acc[4 * c + 3] = __hfma2(v2, u2h2(q.w), acc[4 * c + 3]);
            }
        }
        const __half2* fb1h = reinterpret_cast<const __half2*>(dyn + OFF_FB1H);
        __half2 w2 = __float2half2_rn(w);
#pragma unroll
        for (int t = 0; t < 32; t++) {
            __half2 s2 = silu_h2(__hfma2(w2, acc[t], fb1h[t]));
            svh[(2 * t) * SVH_STR + tid] = __low2half(s2);
            svh[(2 * t + 1) * SVH_STR + tid] = __high2half(s2);
        }
    }
    __syncthreads();

    // ---- epilogue: M[k][d] (half2 chunked), xacc, Dsum ----
    if (tid < 192) {
        int k = tid / 3, d = tid - 3 * k;
        const __half2* sp = reinterpret_cast<const __half2*>(svh + k * SVH_STR);
        const __half2* dph = reinterpret_cast<const __half2*>(sdh + d * 260);
        float accf = 0.f;
#pragma unroll
        for (int ch = 0; ch < 4; ch++) {
            __half2 a2 = hz;
#pragma unroll 8
            for (int m = ch * 32; m < ch * 32 + 32; m++) a2 = __hfma2(sp[m], dph[m], a2);
            accf += __low2float(a2) + __high2float(a2);
        }
        atomicAdd(&g_M[i * 192 + k * 3 + d], accf);
    } else if (tid < 195) {
        int d = tid - 192;
        const float* dp = dyn + OFF_DIR + d * 256;
        const float* pp = dyn + OFF_SPHI;
        float sacc = 0.f;
#pragma unroll 8
        for (int jj = 0; jj < 256; jj++) sacc += dp[jj] * pp[jj];
        atomicAdd(&g_xacc[i * 4 + d], sacc);
    } else if (tid < 198) {
        int d = tid - 195;
        const float* dp = dyn + OFF_DIR + d * 256;
        float sacc = 0.f;
#pragma unroll 8
        for (int jj = 0; jj < 256; jj++) sacc += dp[jj];
        atomicAdd(&g_Dsum[i * 4 + d], sacc);
    }
}

// ---------------- K6: node-level MLPs + outputs -----------------------------------
__global__ void k_final(const float* __restrict__ h, const float* __restrict__ x,
                        const float* __restrict__ ew2, const float* __restrict__ eb2,
                        const float* __restrict__ nw1, const float* __restrict__ nb1,
                        const float* __restrict__ nw2, const float* __restrict__ nb2,
                        const float* __restrict__ pw1, const float* __restrict__ pb1,
                        const float* __restrict__ pw2, const float* __restrict__ pb2,
                        const float* __restrict__ fw2, const float* __restrict__ fb2,
                        float* __restrict__ out, int write_x) {
    __shared__ float sM[192], sq[32], p1[64], nin[192], n1[64], scv[64];
    int i = blockIdx.x, tid = threadIdx.x;
    scv[tid] = g_cv[i * 64 + tid];
    for (int t = tid; t < 192; t += 64) sM[t] = g_M[i * 192 + t];
    __syncthreads();
    if (tid < 32) {
        int c = tid;
        float ds0 = g_Dsum[i * 4 + 0], ds1 = g_Dsum[i * 4 + 1], ds2 = g_Dsum[i * 4 + 2];
        float fb = fb2[c];
        float a0 = fb * ds0, a1 = fb * ds1, a2 = fb * ds2;
#pragma unroll 8
        for (int k = 0; k < 64; k++) {
            float f = fw2[k * 32 + c];
            a0 += f * sM[k * 3 + 0];
            a1 += f * sM[k * 3 + 1];
            a2 += f * sM[k * 3 + 2];
        }
        a0 *= (1.f / 1024.f);
        a1 *= (1.f / 1024.f);
        a2 *= (1.f / 1024.f);
        sq[c] = a0 * a0 + a1 * a1 + a2 * a2;
    }
    __syncthreads();
    {
        float a = g_wsum[i] * eb2[tid];
#pragma unroll 8
        for (int m = 0; m < 64; m++) a += scv[m] * ew2[m * 64 + tid];
        nin[64 + tid] = a;
        float b = pb1[tid];
#pragma unroll
        for (int c = 0; c < 32; c++) b += sq[c] * pw1[c * 64 + tid];
        p1[tid] = silu_f(b);
        nin[tid] = h[i * 64 + tid];
    }
    __syncthreads();
    {
        float a = pb2[tid];
#pragma unroll 8
        for (int m = 0; m < 64; m++) a += p1[m] * pw2[m * 64 + tid];
        nin[128 + tid] = a;
    }
    __syncthreads();
    {
        float a = nb1[tid];
#pragma unroll 8
        for (int m = 0; m < 192; m++) a += nin[m] * nw1[m * 64 + tid];
        n1[tid] = silu_f(a);
    }
    __syncthreads();
    {
        float a = nb2[tid];
#pragma unroll 8
        for (int m = 0; m < 64; m++) a += n1[m] * nw2[m * 64 + tid];
        out[i * 64 + tid] = h[i * 64 + tid] + a;
    }
    if (write_x && tid < 3)
        out[NN * 64 + i * 3 + tid] = x[i * 3 + tid] + g_xacc[i * 4 + tid] * (1.f / 1024.f);
}

// ---------------- host -------------------------------------------------------------
extern "C" void kernel_launch(void* const* d_in, const int* in_sizes, int n_in,
                              void* d_out, int out_size) {
    const float* h = (const float*)d_in[0];
    const float* x = (const float*)d_in[1];
    const float* ew1 = (const float*)d_in[2];
    const float* eb1 = (const float*)d_in[3];
    const float* ew2 = (const float*)d_in[4];
    const float* eb2 = (const float*)d_in[5];
    const float* nw1 = (const float*)d_in[6];
    const float* nb1 = (const float*)d_in[7];
    const float* nw2 = (const float*)d_in[8];
    const float* nb2 = (const float*)d_in[9];
    const float* cw1 = (const float*)d_in[10];
    const float* cb1 = (const float*)d_in[11];
    const float* cw2 = (const float*)d_in[12];
    const float* aw = (const float*)d_in[13];
    const float* ab = (const float*)d_in[14];
    const float* fw1 = (const float*)d_in[15];
    const float* fb1 = (const float*)d_in[16];
    const float* fw2 = (const float*)d_in[17];
    const float* fb2 = (const float*)d_in[18];
    const float* pw1 = (const float*)d_in[19];
    const float* pb1 = (const float*)d_in[20];
    const float* pw2 = (const float*)d_in[21];
    const float* pb2 = (const float*)d_in[22];
    const float* lg = (const float*)d_in[23];
    float* out = (float*)d_out;

    const int K4_SMEM = K4_FLOATS * sizeof(float);  // 58160 B
    cudaFuncSetAttribute(k_pair, cudaFuncAttributeMaxDynamicSharedMemorySize, K4_SMEM);

    int write_x = (out_size >= NN * 64 + NN * 3) ? 1 : 0;

    k_prep<<<PREP_GRID, 64>>>(h, ew1, eb1, ew2, eb2, cw1, cb1, fw1, aw, ab);
    k_edge_attn<<<NN, 256>>>(x, lg);
    k_pair<<<dim3(NN / 256, NN), 256, K4_SMEM>>>(x, fb1, cw2);
    k_final<<<NN, 64>>>(h, x, ew2, eb2, nw1, nb1, nw2, nb2, pw1, pb1, pw2, pb2,
                        fw2, fb2, out, write_x);
}